// round 5
// baseline (speedup 1.0000x reference)
#include <cuda_runtime.h>
#include <cstdint>
#include <math.h>

// Problem dims
#define B_  16
#define S_  128
#define BS  2048      // B*S
#define D_  256
#define H_  256
#define V_  32000
#define K2H 512       // 2*H
#define NCTA_LSTM 64

// ---------------- scratch (device globals; no allocation allowed) -----------
__device__ float g_emb[BS * D_];          // [2048,256] gathered embeddings
__device__ float g_pre[BS * 2048];        // cols 0..1023: xp_f ; 1024..2047: backward pre-acts
__device__ float g_out[BS * K2H];         // [2048,512] = concat(hf, hb)
__device__ float g_h[2][B_ * H_];         // double-buffered forward hidden state
__device__ int   g_is64;                  // token dtype flag
__device__ int          g_cnt;            // global barrier counter
__device__ volatile int g_flag;           // global barrier sense flag

// ---------------- helpers ---------------------------------------------------
__device__ __forceinline__ float sigf(float x) { return 1.0f / (1.0f + expf(-x)); }

// ---------------- dtype detect: int64 tokens have zero high words -----------
__global__ void detect_kernel(const int* __restrict__ xi) {
    __shared__ int red[256];
    int acc = 0;
    // Only touch the first 2048 int32 words (safe for both int32 and int64 buffers).
    for (int i = threadIdx.x; i < 1024; i += 256) acc |= xi[2 * i + 1];
    red[threadIdx.x] = acc;
    __syncthreads();
    for (int s = 128; s > 0; s >>= 1) {
        if (threadIdx.x < s) red[threadIdx.x] |= red[threadIdx.x + s];
        __syncthreads();
    }
    if (threadIdx.x == 0) g_is64 = (red[0] == 0) ? 1 : 0;
}

// ---------------- per-launch state init (replay-deterministic) --------------
__global__ void zero_state() {
    int i = blockIdx.x * 256 + threadIdx.x;
    if (i < B_ * H_) g_h[0][i] = 0.0f;
    if (i == 0) { g_cnt = 0; g_flag = 0; }
}

// ---------------- embedding gather ------------------------------------------
__global__ void gather_kernel(const int* __restrict__ xi,
                              const float4* __restrict__ emb4) {
    int idx = blockIdx.x * 256 + threadIdx.x;     // 2048 rows * 64 float4
    int r = idx >> 6, c = idx & 63;
    long long tok;
    if (g_is64) tok = ((const long long*)xi)[r];
    else        tok = (long long)xi[r];
    ((float4*)g_emb)[r * 64 + c] = emb4[(size_t)tok * 64 + c];
}

// ---------------- input projection GEMM: [2048,256] x [2048,256]^T ----------
// N rows 0..1023 -> w_ih_f (store xp_f + b_ih_f + b_hh_f)
// N rows 1024..2047 -> w_ih_b (store backward pre-act + b_ih_b + b_hh_b)
__global__ __launch_bounds__(256, 2)
void proj_gemm(const float* __restrict__ wf, const float* __restrict__ wb,
               const float* __restrict__ bif, const float* __restrict__ bhf,
               const float* __restrict__ bib, const float* __restrict__ bhb) {
    __shared__ float As[16][132];
    __shared__ float Bs[16][132];
    int m0 = blockIdx.y * 128, n0 = blockIdx.x * 128;
    const float *Bw, *bb1, *bb2;
    if (n0 < 1024) { Bw = wf + (size_t)n0 * 256;          bb1 = bif + n0;          bb2 = bhf + n0; }
    else           { Bw = wb + (size_t)(n0 - 1024) * 256; bb1 = bib + (n0 - 1024); bb2 = bhb + (n0 - 1024); }

    int tid = threadIdx.x;
    int tm = (tid >> 4) << 3, tn = (tid & 15) << 3;
    float acc[8][8] = {};

    for (int k0 = 0; k0 < 256; k0 += 16) {
#pragma unroll
        for (int i = 0; i < 2; i++) {
            int q = tid + i * 256;
            int row = q >> 2, qc = q & 3;
            float4 va = *(const float4*)(g_emb + (size_t)(m0 + row) * 256 + k0 + qc * 4);
            float4 vb = *(const float4*)(Bw + (size_t)row * 256 + k0 + qc * 4);
            As[qc * 4 + 0][row] = va.x; As[qc * 4 + 1][row] = va.y;
            As[qc * 4 + 2][row] = va.z; As[qc * 4 + 3][row] = va.w;
            Bs[qc * 4 + 0][row] = vb.x; Bs[qc * 4 + 1][row] = vb.y;
            Bs[qc * 4 + 2][row] = vb.z; Bs[qc * 4 + 3][row] = vb.w;
        }
        __syncthreads();
#pragma unroll
        for (int k = 0; k < 16; k++) {
            float a[8], b[8];
            *(float4*)(a)     = *(const float4*)&As[k][tm];
            *(float4*)(a + 4) = *(const float4*)&As[k][tm + 4];
            *(float4*)(b)     = *(const float4*)&Bs[k][tn];
            *(float4*)(b + 4) = *(const float4*)&Bs[k][tn + 4];
#pragma unroll
            for (int ii = 0; ii < 8; ii++)
#pragma unroll
                for (int jj = 0; jj < 8; jj++) acc[ii][jj] += a[ii] * b[jj];
        }
        __syncthreads();
    }
#pragma unroll
    for (int ii = 0; ii < 8; ii++) {
        int r = m0 + tm + ii;
#pragma unroll
        for (int jj = 0; jj < 8; jj += 4) {
            float4 o;
            o.x = acc[ii][jj + 0] + bb1[tn + jj + 0] + bb2[tn + jj + 0];
            o.y = acc[ii][jj + 1] + bb1[tn + jj + 1] + bb2[tn + jj + 1];
            o.z = acc[ii][jj + 2] + bb1[tn + jj + 2] + bb2[tn + jj + 2];
            o.w = acc[ii][jj + 3] + bb1[tn + jj + 3] + bb2[tn + jj + 3];
            *(float4*)(g_pre + (size_t)r * 2048 + n0 + tn + jj) = o;
        }
    }
}

// ---------------- backward direction: single cell step from zero state ------
__global__ void hb_kernel() {
    int idx = blockIdx.x * 256 + threadIdx.x;   // 2048 * 256
    int r = idx >> 8, j = idx & 255;
    const float* p = g_pre + (size_t)r * 2048 + 1024;
    float ig = sigf(p[j]);
    float gg = tanhf(p[512 + j]);
    float og = sigf(p[768 + j]);
    g_out[(size_t)r * K2H + 256 + j] = og * tanhf(ig * gg);
}

// ---------------- forward LSTM: single persistent kernel --------------------
// 64 CTAs (all co-resident: <=34KB smem, 256 thr). CTA owns 4 hidden units
// (16 gate rows), weights cached in smem ONCE; cell state in registers.
// Cross-CTA h exchange through L2 (__ldcg) + sense-reversing global barrier.
__global__ __launch_bounds__(256, 1)
void lstm_persist(const float* __restrict__ w_hh) {
    __shared__ float sw[16][260];
    __shared__ float sh[16][260];
    __shared__ float spre[4][16][4];
    __shared__ int sense;
    int tid = threadIdx.x;
    int j0 = blockIdx.x * 4;
    if (tid == 0) sense = 0;

    // Load this CTA's 16 gate rows of w_hh once (16 x 256 floats).
#pragma unroll
    for (int i = 0; i < 4; i++) {
        int q = tid + i * 256;          // 1024 float4 slots
        int rr = q >> 6, kc = q & 63;
        int gi = rr >> 2, jj = rr & 3;
        int grow = gi * 256 + j0 + jj;  // gate row in w_hh [1024,256]
        float4 wv = ((const float4*)w_hh)[grow * 64 + kc];
        *(float4*)&sw[rr][kc * 4] = wv;
    }

    float creg = 0.0f;                  // cell state for (b=tid>>2, jj=tid&3), tid<64

    for (int t = 0; t < S_; t++) {
        const float4* __restrict__ h_in = (const float4*)g_h[t & 1];
        float* h_out = g_h[(t + 1) & 1];

        // Load full h state [16,256] via L2 (bypass non-coherent L1).
#pragma unroll
        for (int i = 0; i < 4; i++) {
            int q = tid + i * 256;
            int rr = q >> 6, kc = q & 63;       // rr = batch
            float4 hv = __ldcg(h_in + rr * 64 + kc);
            *(float4*)&sh[rr][kc * 4] = hv;
        }
        __syncthreads();

        {   // each thread: one (batch, gate-row) dot product over H=256
            int b = tid >> 4, rr = tid & 15;
            int gi = rr >> 2, jj = rr & 3;
            const float4* wr = (const float4*)&sw[rr][0];
            const float4* hr = (const float4*)&sh[b][0];
            float acc = 0.0f;
#pragma unroll 16
            for (int kc = 0; kc < 64; kc++) {
                float4 w = wr[kc], h = hr[kc];
                acc += w.x * h.x + w.y * h.y + w.z * h.z + w.w * h.w;
            }
            int r = b * S_ + t;
            acc += g_pre[(size_t)r * 2048 + gi * 256 + j0 + jj];
            spre[gi][b][jj] = acc;
        }
        __syncthreads();

        if (tid < 64) {
            int b = tid >> 2, jj = tid & 3;
            int j = j0 + jj;
            float ig = sigf(spre[0][b][jj]);
            float fg = sigf(spre[1][b][jj]);
            float gg = tanhf(spre[2][b][jj]);
            float og = sigf(spre[3][b][jj]);
            creg = fg * creg + ig * gg;
            float h = og * tanhf(creg);
            h_out[b * 256 + j] = h;
            g_out[(size_t)(b * S_ + t) * K2H + j] = h;
            __threadfence();            // release h_out before barrier arrival
        }

        // -------- global barrier (sense-reversing) --------
        __syncthreads();
        if (tid == 0) {
            int s = sense ^ 1;
            sense = s;
            int v = atomicAdd(&g_cnt, 1);
            if (v == NCTA_LSTM - 1) {
                g_cnt = 0;
                __threadfence();
                g_flag = s;
            } else {
                while (g_flag != s) __nanosleep(32);
            }
            __threadfence();            // acquire before next step's h reads
        }
        __syncthreads();
    }
}

// ---------------- FC logits GEMM: [2048,512] x [32000,512]^T + fc_b ---------
__global__ __launch_bounds__(256, 2)
void fc_gemm(const float* __restrict__ W, const float* __restrict__ bias,
             float* __restrict__ C) {
    __shared__ float As[16][132];
    __shared__ float Bs[16][132];
    int m0 = blockIdx.y * 128, n0 = blockIdx.x * 128;
    int tid = threadIdx.x;
    int tm = (tid >> 4) << 3, tn = (tid & 15) << 3;
    int row = tid >> 2, qc = tid & 3;          // row in 0..63, plus row+64 slot
    float acc[8][8] = {};

    // preload first k-tile
    float4 pa0 = *(const float4*)(g_out + (size_t)(m0 + row) * 512 + qc * 4);
    float4 pa1 = *(const float4*)(g_out + (size_t)(m0 + row + 64) * 512 + qc * 4);
    float4 pb0 = *(const float4*)(W + (size_t)(n0 + row) * 512 + qc * 4);
    float4 pb1 = *(const float4*)(W + (size_t)(n0 + row + 64) * 512 + qc * 4);
    As[qc * 4 + 0][row] = pa0.x; As[qc * 4 + 1][row] = pa0.y;
    As[qc * 4 + 2][row] = pa0.z; As[qc * 4 + 3][row] = pa0.w;
    As[qc * 4 + 0][row + 64] = pa1.x; As[qc * 4 + 1][row + 64] = pa1.y;
    As[qc * 4 + 2][row + 64] = pa1.z; As[qc * 4 + 3][row + 64] = pa1.w;
    Bs[qc * 4 + 0][row] = pb0.x; Bs[qc * 4 + 1][row] = pb0.y;
    Bs[qc * 4 + 2][row] = pb0.z; Bs[qc * 4 + 3][row] = pb0.w;
    Bs[qc * 4 + 0][row + 64] = pb1.x; Bs[qc * 4 + 1][row + 64] = pb1.y;
    Bs[qc * 4 + 2][row + 64] = pb1.z; Bs[qc * 4 + 3][row + 64] = pb1.w;
    __syncthreads();

#pragma unroll 1
    for (int kt = 0; kt < 32; kt++) {
        bool lastTile = (kt == 31);
        float4 na0, na1, nb0, nb1;
        if (!lastTile) {
            int k0 = (kt + 1) * 16;
            na0 = *(const float4*)(g_out + (size_t)(m0 + row) * 512 + k0 + qc * 4);
            na1 = *(const float4*)(g_out + (size_t)(m0 + row + 64) * 512 + k0 + qc * 4);
            nb0 = *(const float4*)(W + (size_t)(n0 + row) * 512 + k0 + qc * 4);
            nb1 = *(const float4*)(W + (size_t)(n0 + row + 64) * 512 + k0 + qc * 4);
        }
#pragma unroll
        for (int k = 0; k < 16; k++) {
            float a[8], b[8];
            *(float4*)(a)     = *(const float4*)&As[k][tm];
            *(float4*)(a + 4) = *(const float4*)&As[k][tm + 4];
            *(float4*)(b)     = *(const float4*)&Bs[k][tn];
            *(float4*)(b + 4) = *(const float4*)&Bs[k][tn + 4];
#pragma unroll
            for (int ii = 0; ii < 8; ii++)
#pragma unroll
                for (int jj = 0; jj < 8; jj++) acc[ii][jj] += a[ii] * b[jj];
        }
        __syncthreads();
        if (!lastTile) {
            As[qc * 4 + 0][row] = na0.x; As[qc * 4 + 1][row] = na0.y;
            As[qc * 4 + 2][row] = na0.z; As[qc * 4 + 3][row] = na0.w;
            As[qc * 4 + 0][row + 64] = na1.x; As[qc * 4 + 1][row + 64] = na1.y;
            As[qc * 4 + 2][row + 64] = na1.z; As[qc * 4 + 3][row + 64] = na1.w;
            Bs[qc * 4 + 0][row] = nb0.x; Bs[qc * 4 + 1][row] = nb0.y;
            Bs[qc * 4 + 2][row] = nb0.z; Bs[qc * 4 + 3][row] = nb0.w;
            Bs[qc * 4 + 0][row + 64] = nb1.x; Bs[qc * 4 + 1][row + 64] = nb1.y;
            Bs[qc * 4 + 2][row + 64] = nb1.z; Bs[qc * 4 + 3][row + 64] = nb1.w;
            __syncthreads();
        }
    }

#pragma unroll
    for (int ii = 0; ii < 8; ii++) {
        size_t r = (size_t)(m0 + tm + ii);
#pragma unroll
        for (int jj = 0; jj < 8; jj += 4) {
            int n = n0 + tn + jj;
            float4 o;
            o.x = acc[ii][jj + 0] + bias[n + 0];
            o.y = acc[ii][jj + 1] + bias[n + 1];
            o.z = acc[ii][jj + 2] + bias[n + 2];
            o.w = acc[ii][jj + 3] + bias[n + 3];
            *(float4*)(C + r * V_ + n) = o;
        }
    }
}

// ---------------- launch ----------------------------------------------------
extern "C" void kernel_launch(void* const* d_in, const int* in_sizes, int n_in,
                              void* d_out, int out_size) {
    const int*   x      = (const int*)d_in[0];     // int32 or int64 (detected)
    const float* embed  = (const float*)d_in[1];
    const float* w_ih_f = (const float*)d_in[2];
    const float* w_hh_f = (const float*)d_in[3];
    const float* b_ih_f = (const float*)d_in[4];
    const float* b_hh_f = (const float*)d_in[5];
    const float* w_ih_b = (const float*)d_in[6];
    // d_in[7] = w_hh_b : multiplied by the zero initial state -> unused
    const float* b_ih_b = (const float*)d_in[8];
    const float* b_hh_b = (const float*)d_in[9];
    const float* fc_w   = (const float*)d_in[10];
    const float* fc_b   = (const float*)d_in[11];
    float* out = (float*)d_out;

    detect_kernel<<<1, 256>>>(x);
    zero_state<<<16, 256>>>();
    gather_kernel<<<512, 256>>>(x, (const float4*)embed);
    proj_gemm<<<dim3(16, 16), 256>>>(w_ih_f, w_ih_b, b_ih_f, b_hh_f, b_ih_b, b_hh_b);
    hb_kernel<<<2048, 256>>>();
    lstm_persist<<<NCTA_LSTM, 256>>>(w_hh_f);
    fc_gemm<<<dim3(250, 16), 256>>>(fc_w, fc_b, out);
    (void)in_sizes; (void)n_in; (void)out_size;
}

// round 7
// speedup vs baseline: 1.4477x; 1.4477x over previous
#include <cuda_runtime.h>
#include <cuda_bf16.h>
#include <cstdint>
#include <math.h>

// Problem dims
#define B_  16
#define S_  128
#define BS  2048      // B*S
#define D_  256
#define H_  256
#define V_  32000
#define K2H 512       // 2*H
#define NCTA_LSTM 64

// FC GEMM (mma.sync bf16): C[2048,32000] = A2[2048,1536] x W2eff[32000,1536]^T
// A2 = [A_hi | A_hi | A_lo]; W2 = [W_hi | W_lo]; k-segment 3 re-reads W_hi.
#define FC_KTILES 48            // 48 x 32 = 1536
#define FC_KC 32                // k per mainloop iter
#define FC_STAGES 4
#define FC_ROWB 80              // padded smem row bytes (32 bf16 = 64B data + 16B pad)
#define FC_STAGE_BYTES (128 * FC_ROWB)          // 10240
#define FC_SMEM (FC_STAGES * FC_STAGE_BYTES * 2) // 81920 (epilogue aliases this)

// ---------------- scratch (device globals; no allocation allowed) -----------
__device__ float g_emb[BS * D_];
__device__ float g_pre[BS * 2048];
__device__ float g_out[BS * K2H];
__device__ float g_h[2][B_ * H_];
__device__ __nv_bfloat16 g_a2[BS * 1536];            // [2048,1536] = [A_hi|A_hi|A_lo]
__device__ __nv_bfloat16 g_w2[(size_t)V_ * 1024];    // [32000,1024] = [W_hi|W_lo]
__device__ int   g_is64;
__device__ int          g_cnt;
__device__ volatile int g_flag;

// ---------------- helpers ---------------------------------------------------
__device__ __forceinline__ float sigf(float x) { return 1.0f / (1.0f + expf(-x)); }

__device__ __forceinline__ uint32_t smem_u32(const void* p) {
    uint32_t a;
    asm("{ .reg .u64 t; cvta.to.shared.u64 t, %1; cvt.u32.u64 %0, t; }" : "=r"(a) : "l"(p));
    return a;
}
__device__ __forceinline__ void cp_async16(uint32_t s, const void* g) {
    asm volatile("cp.async.cg.shared.global [%0], [%1], 16;" :: "r"(s), "l"(g));
}
#define CP_COMMIT() asm volatile("cp.async.commit_group;" ::: "memory")
#define CP_WAIT(n)  asm volatile("cp.async.wait_group %0;" :: "n"(n) : "memory")

__device__ __forceinline__ void ldsm_x4(uint32_t* r, uint32_t addr) {
    asm volatile("ldmatrix.sync.aligned.m8n8.x4.shared.b16 {%0,%1,%2,%3}, [%4];"
                 : "=r"(r[0]), "=r"(r[1]), "=r"(r[2]), "=r"(r[3]) : "r"(addr));
}
__device__ __forceinline__ void mma16816(float* c, const uint32_t* a,
                                         uint32_t b0, uint32_t b1) {
    asm volatile(
        "mma.sync.aligned.m16n8k16.row.col.f32.bf16.bf16.f32 "
        "{%0,%1,%2,%3}, {%4,%5,%6,%7}, {%8,%9}, {%0,%1,%2,%3};"
        : "+f"(c[0]), "+f"(c[1]), "+f"(c[2]), "+f"(c[3])
        : "r"(a[0]), "r"(a[1]), "r"(a[2]), "r"(a[3]), "r"(b0), "r"(b1));
}

// ---------------- dtype detect: int64 tokens have zero high words -----------
__global__ void detect_kernel(const int* __restrict__ xi) {
    __shared__ int red[256];
    int acc = 0;
    for (int i = threadIdx.x; i < 1024; i += 256) acc |= xi[2 * i + 1];
    red[threadIdx.x] = acc;
    __syncthreads();
    for (int s = 128; s > 0; s >>= 1) {
        if (threadIdx.x < s) red[threadIdx.x] |= red[threadIdx.x + s];
        __syncthreads();
    }
    if (threadIdx.x == 0) g_is64 = (red[0] == 0) ? 1 : 0;
}

// ---------------- per-launch state init (replay-deterministic) --------------
__global__ void zero_state() {
    int i = blockIdx.x * 256 + threadIdx.x;
    if (i < B_ * H_) g_h[0][i] = 0.0f;
    if (i == 0) { g_cnt = 0; g_flag = 0; }
}

// ---------------- embedding gather ------------------------------------------
__global__ void gather_kernel(const int* __restrict__ xi,
                              const float4* __restrict__ emb4) {
    int idx = blockIdx.x * 256 + threadIdx.x;
    int r = idx >> 6, c = idx & 63;
    long long tok;
    if (g_is64) tok = ((const long long*)xi)[r];
    else        tok = (long long)xi[r];
    ((float4*)g_emb)[r * 64 + c] = emb4[(size_t)tok * 64 + c];
}

// ---------------- input projection GEMM: [2048,256] x [2048,256]^T ----------
__global__ __launch_bounds__(256, 2)
void proj_gemm(const float* __restrict__ wf, const float* __restrict__ wb,
               const float* __restrict__ bif, const float* __restrict__ bhf,
               const float* __restrict__ bib, const float* __restrict__ bhb) {
    __shared__ float As[16][132];
    __shared__ float Bs[16][132];
    int m0 = blockIdx.y * 128, n0 = blockIdx.x * 128;
    const float *Bw, *bb1, *bb2;
    if (n0 < 1024) { Bw = wf + (size_t)n0 * 256;          bb1 = bif + n0;          bb2 = bhf + n0; }
    else           { Bw = wb + (size_t)(n0 - 1024) * 256; bb1 = bib + (n0 - 1024); bb2 = bhb + (n0 - 1024); }

    int tid = threadIdx.x;
    int tm = (tid >> 4) << 3, tn = (tid & 15) << 3;
    float acc[8][8] = {};

    for (int k0 = 0; k0 < 256; k0 += 16) {
#pragma unroll
        for (int i = 0; i < 2; i++) {
            int q = tid + i * 256;
            int row = q >> 2, qc = q & 3;
            float4 va = *(const float4*)(g_emb + (size_t)(m0 + row) * 256 + k0 + qc * 4);
            float4 vb = *(const float4*)(Bw + (size_t)row * 256 + k0 + qc * 4);
            As[qc * 4 + 0][row] = va.x; As[qc * 4 + 1][row] = va.y;
            As[qc * 4 + 2][row] = va.z; As[qc * 4 + 3][row] = va.w;
            Bs[qc * 4 + 0][row] = vb.x; Bs[qc * 4 + 1][row] = vb.y;
            Bs[qc * 4 + 2][row] = vb.z; Bs[qc * 4 + 3][row] = vb.w;
        }
        __syncthreads();
#pragma unroll
        for (int k = 0; k < 16; k++) {
            float a[8], b[8];
            *(float4*)(a)     = *(const float4*)&As[k][tm];
            *(float4*)(a + 4) = *(const float4*)&As[k][tm + 4];
            *(float4*)(b)     = *(const float4*)&Bs[k][tn];
            *(float4*)(b + 4) = *(const float4*)&Bs[k][tn + 4];
#pragma unroll
            for (int ii = 0; ii < 8; ii++)
#pragma unroll
                for (int jj = 0; jj < 8; jj++) acc[ii][jj] += a[ii] * b[jj];
        }
        __syncthreads();
    }
#pragma unroll
    for (int ii = 0; ii < 8; ii++) {
        int r = m0 + tm + ii;
#pragma unroll
        for (int jj = 0; jj < 8; jj += 4) {
            float4 o;
            o.x = acc[ii][jj + 0] + bb1[tn + jj + 0] + bb2[tn + jj + 0];
            o.y = acc[ii][jj + 1] + bb1[tn + jj + 1] + bb2[tn + jj + 1];
            o.z = acc[ii][jj + 2] + bb1[tn + jj + 2] + bb2[tn + jj + 2];
            o.w = acc[ii][jj + 3] + bb1[tn + jj + 3] + bb2[tn + jj + 3];
            *(float4*)(g_pre + (size_t)r * 2048 + n0 + tn + jj) = o;
        }
    }
}

// ---------------- backward direction: single cell step from zero state ------
__global__ void hb_kernel() {
    int idx = blockIdx.x * 256 + threadIdx.x;
    int r = idx >> 8, j = idx & 255;
    const float* p = g_pre + (size_t)r * 2048 + 1024;
    float ig = sigf(p[j]);
    float gg = tanhf(p[512 + j]);
    float og = sigf(p[768 + j]);
    g_out[(size_t)r * K2H + 256 + j] = og * tanhf(ig * gg);
}

// ---------------- forward LSTM: single persistent kernel --------------------
__global__ __launch_bounds__(256, 1)
void lstm_persist(const float* __restrict__ w_hh) {
    __shared__ float sw[16][260];
    __shared__ float sh[16][260];
    __shared__ float spre[4][16][4];
    __shared__ int sense;
    int tid = threadIdx.x;
    int j0 = blockIdx.x * 4;
    if (tid == 0) sense = 0;

#pragma unroll
    for (int i = 0; i < 4; i++) {
        int q = tid + i * 256;
        int rr = q >> 6, kc = q & 63;
        int gi = rr >> 2, jj = rr & 3;
        int grow = gi * 256 + j0 + jj;
        float4 wv = ((const float4*)w_hh)[grow * 64 + kc];
        *(float4*)&sw[rr][kc * 4] = wv;
    }

    float creg = 0.0f;

    for (int t = 0; t < S_; t++) {
        const float4* __restrict__ h_in = (const float4*)g_h[t & 1];
        float* h_out = g_h[(t + 1) & 1];

#pragma unroll
        for (int i = 0; i < 4; i++) {
            int q = tid + i * 256;
            int rr = q >> 6, kc = q & 63;
            float4 hv = __ldcg(h_in + rr * 64 + kc);
            *(float4*)&sh[rr][kc * 4] = hv;
        }
        __syncthreads();

        {
            int b = tid >> 4, rr = tid & 15;
            int gi = rr >> 2, jj = rr & 3;
            const float4* wr = (const float4*)&sw[rr][0];
            const float4* hr = (const float4*)&sh[b][0];
            float acc = 0.0f;
#pragma unroll 16
            for (int kc = 0; kc < 64; kc++) {
                float4 w = wr[kc], h = hr[kc];
                acc += w.x * h.x + w.y * h.y + w.z * h.z + w.w * h.w;
            }
            int r = b * S_ + t;
            acc += g_pre[(size_t)r * 2048 + gi * 256 + j0 + jj];
            spre[gi][b][jj] = acc;
        }
        __syncthreads();

        if (tid < 64) {
            int b = tid >> 2, jj = tid & 3;
            int j = j0 + jj;
            float ig = sigf(spre[0][b][jj]);
            float fg = sigf(spre[1][b][jj]);
            float gg = tanhf(spre[2][b][jj]);
            float og = sigf(spre[3][b][jj]);
            creg = fg * creg + ig * gg;
            float h = og * tanhf(creg);
            h_out[b * 256 + j] = h;
            g_out[(size_t)(b * S_ + t) * K2H + j] = h;
            __threadfence();
        }

        __syncthreads();
        if (tid == 0) {
            int s = sense ^ 1;
            sense = s;
            int v = atomicAdd(&g_cnt, 1);
            if (v == NCTA_LSTM - 1) {
                g_cnt = 0;
                __threadfence();
                g_flag = s;
            } else {
                while (g_flag != s) __nanosleep(32);
            }
            __threadfence();
        }
        __syncthreads();
    }
}

// ---------------- fp32 -> bf16 hi/lo conversions -----------------------------
__global__ void convA() {
    int idx = blockIdx.x * 256 + threadIdx.x;
    int r = idx >> 8, kp = idx & 255;
    float2 v = *(const float2*)(g_out + (size_t)r * 512 + kp * 2);
    __nv_bfloat16 h0 = __float2bfloat16(v.x), h1 = __float2bfloat16(v.y);
    __nv_bfloat16 l0 = __float2bfloat16(v.x - __bfloat162float(h0));
    __nv_bfloat16 l1 = __float2bfloat16(v.y - __bfloat162float(h1));
    __nv_bfloat162 hp; hp.x = h0; hp.y = h1;
    __nv_bfloat162 lp; lp.x = l0; lp.y = l1;
    __nv_bfloat162* o = (__nv_bfloat162*)(g_a2 + (size_t)r * 1536);
    o[kp] = hp; o[256 + kp] = hp; o[512 + kp] = lp;
}

__global__ void convW(const float* __restrict__ W) {
    size_t idx = (size_t)blockIdx.x * 256 + threadIdx.x;
    size_t r = idx >> 8; int kp = (int)(idx & 255);
    float2 v = *(const float2*)(W + r * 512 + kp * 2);
    __nv_bfloat16 h0 = __float2bfloat16(v.x), h1 = __float2bfloat16(v.y);
    __nv_bfloat16 l0 = __float2bfloat16(v.x - __bfloat162float(h0));
    __nv_bfloat16 l1 = __float2bfloat16(v.y - __bfloat162float(h1));
    __nv_bfloat162 hp; hp.x = h0; hp.y = h1;
    __nv_bfloat162 lp; lp.x = l0; lp.y = l1;
    __nv_bfloat162* o = (__nv_bfloat162*)(g_w2 + r * 1024);
    o[kp] = hp; o[256 + kp] = lp;
}

// ---------------- FC GEMM via mma.sync (HMMA bf16) ---------------------------
// CTA 128x128, 8 warps (2M x 4N), warp tile 64x32, 4-stage cp.async, KC=32.
static __device__ __forceinline__
void fc_load_stage(uint32_t sbase, int tid, int m0, int n0, int kt) {
    int slot = kt & 3;
    uint32_t sa = sbase + slot * FC_STAGE_BYTES;
    uint32_t sb = sbase + FC_STAGES * FC_STAGE_BYTES + slot * FC_STAGE_BYTES;
    int ke = kt * FC_KC;
    int kB = (ke < 1024) ? ke : ke - 1024;           // seg3 re-reads W_hi
    const __nv_bfloat16* ag = g_a2 + (size_t)m0 * 1536 + ke;
    const __nv_bfloat16* bg = g_w2 + (size_t)n0 * 1024 + kB;
#pragma unroll
    for (int i = 0; i < 2; i++) {
        int ch = tid + i * 256;                      // 512 chunks each
        int r = ch >> 2, c = ch & 3;
        cp_async16(sa + r * FC_ROWB + c * 16, ag + (size_t)r * 1536 + c * 8);
        cp_async16(sb + r * FC_ROWB + c * 16, bg + (size_t)r * 1024 + c * 8);
    }
}

__global__ __launch_bounds__(256, 1)
void fc_gemm_mma(const float* __restrict__ bias, float* __restrict__ C) {
    extern __shared__ char smem[];
    uint32_t sbase = smem_u32(smem);
    int tid = threadIdx.x, wid = tid >> 5, lane = tid & 31;
    int m0 = blockIdx.x * 128;                       // 16 tiles (fastest -> W L2 reuse)
    int n0 = blockIdx.y * 128;                       // 250 tiles
    int wm = (wid >> 2) * 64;                        // warp m base (0/64)
    int wn = (wid & 3) * 32;                         // warp n base (0..96)

    float acc[4][4][4];
#pragma unroll
    for (int a = 0; a < 4; a++)
#pragma unroll
        for (int b = 0; b < 4; b++)
#pragma unroll
            for (int r = 0; r < 4; r++) acc[a][b][r] = 0.0f;

    // per-lane ldmatrix base offsets within a stage
    uint32_t aOff = (uint32_t)(wm + (lane & 15)) * FC_ROWB + (uint32_t)(lane >> 4) * 16;
    int bn = (lane & 7) + ((lane >> 4) & 1) * 8;
    uint32_t bOff = (uint32_t)(wn + bn) * FC_ROWB + (uint32_t)((lane >> 3) & 1) * 16;

    // prologue: stages 0..2
    fc_load_stage(sbase, tid, m0, n0, 0); CP_COMMIT();
    fc_load_stage(sbase, tid, m0, n0, 1); CP_COMMIT();
    fc_load_stage(sbase, tid, m0, n0, 2); CP_COMMIT();

#pragma unroll 1
    for (int kt = 0; kt < FC_KTILES; kt++) {
        CP_WAIT(2);
        __syncthreads();
        if (kt + 3 < FC_KTILES) fc_load_stage(sbase, tid, m0, n0, kt + 3);
        CP_COMMIT();                                   // empty-commit keeps count

        int slot = kt & 3;
        uint32_t aS = sbase + slot * FC_STAGE_BYTES;
        uint32_t bS = sbase + FC_STAGES * FC_STAGE_BYTES + slot * FC_STAGE_BYTES;
#pragma unroll
        for (int ks = 0; ks < 2; ks++) {
            uint32_t k2 = (uint32_t)(ks * 32);       // 16 bf16 = 32 bytes
            uint32_t af[4][4];
#pragma unroll
            for (int mb = 0; mb < 4; mb++)
                ldsm_x4(af[mb], aS + aOff + (uint32_t)mb * 16 * FC_ROWB + k2);
            uint32_t bfr[2][4];
#pragma unroll
            for (int nq = 0; nq < 2; nq++)
                ldsm_x4(bfr[nq], bS + bOff + (uint32_t)nq * 16 * FC_ROWB + k2);
#pragma unroll
            for (int mb = 0; mb < 4; mb++)
#pragma unroll
                for (int nb = 0; nb < 4; nb++)
                    mma16816(acc[mb][nb], af[mb],
                             bfr[nb >> 1][(nb & 1) * 2], bfr[nb >> 1][(nb & 1) * 2 + 1]);
        }
        __syncthreads();
    }

    // epilogue: stage through smem (aliases pipeline buffers), coalesced store
    float* epi = (float*)smem;                        // [128][132]
    __syncthreads();
    int er = lane >> 2, ec = (lane & 3) * 2;
#pragma unroll
    for (int mb = 0; mb < 4; mb++) {
#pragma unroll
        for (int nb = 0; nb < 4; nb++) {
            int m = wm + mb * 16 + er;
            int n = wn + nb * 8 + ec;
            *(float2*)&epi[m * 132 + n]       = make_float2(acc[mb][nb][0], acc[mb][nb][1]);
            *(float2*)&epi[(m + 8) * 132 + n] = make_float2(acc[mb][nb][2], acc[mb][nb][3]);
        }
    }
    __syncthreads();

    float4 bv = *(const float4*)(bias + n0 + lane * 4);
#pragma unroll 1
    for (int r = 0; r < 16; r++) {
        int m = wid * 16 + r;
        float4 v = *(float4*)&epi[m * 132 + lane * 4];
        v.x += bv.x; v.y += bv.y; v.z += bv.z; v.w += bv.w;
        *(float4*)&C[(size_t)(m0 + m) * V_ + n0 + lane * 4] = v;
    }
}

// ---------------- launch ----------------------------------------------------
extern "C" void kernel_launch(void* const* d_in, const int* in_sizes, int n_in,
                              void* d_out, int out_size) {
    const int*   x      = (const int*)d_in[0];
    const float* embed  = (const float*)d_in[1];
    const float* w_ih_f = (const float*)d_in[2];
    const float* w_hh_f = (const float*)d_in[3];
    const float* b_ih_f = (const float*)d_in[4];
    const float* b_hh_f = (const float*)d_in[5];
    const float* w_ih_b = (const float*)d_in[6];
    // d_in[7] = w_hh_b : multiplied by the zero initial state -> unused
    const float* b_ih_b = (const float*)d_in[8];
    const float* b_hh_b = (const float*)d_in[9];
    const float* fc_w   = (const float*)d_in[10];
    const float* fc_b   = (const float*)d_in[11];
    float* out = (float*)d_out;

    cudaFuncSetAttribute(fc_gemm_mma, cudaFuncAttributeMaxDynamicSharedMemorySize, FC_SMEM);

    detect_kernel<<<1, 256>>>(x);
    zero_state<<<16, 256>>>();
    gather_kernel<<<512, 256>>>(x, (const float4*)embed);
    convW<<<V_ * 512 / 2 / 256, 256>>>(fc_w);
    proj_gemm<<<dim3(16, 16), 256>>>(w_ih_f, w_ih_b, b_ih_f, b_hh_f, b_ih_b, b_hh_b);
    hb_kernel<<<2048, 256>>>();
    lstm_persist<<<NCTA_LSTM, 256>>>(w_hh_f);
    convA<<<2048, 256>>>();
    fc_gemm_mma<<<dim3(16, 250), 256, FC_SMEM>>>(fc_b, out);
    (void)in_sizes; (void)n_in; (void)out_size;
}

// round 8
// speedup vs baseline: 1.4484x; 1.0005x over previous
#include <cuda_runtime.h>
#include <cuda_bf16.h>
#include <cstdint>
#include <math.h>

// Problem dims
#define B_  16
#define S_  128
#define BS  2048      // B*S
#define D_  256
#define H_  256
#define V_  32000
#define K2H 512       // 2*H
#define NCTA_LSTM 64

// FC GEMM (mma.sync bf16): C[2048,32000] = A2[2048,1536] x W2eff[32000,1536]^T
// A2 = [A_hi | A_hi | A_lo]; W2 = [W_hi | W_lo]; k-segment 3 re-reads W_hi.
// CTA tile 128(M) x 256(N), 8 warps (2m x 4n), warp tile 64x64.
#define FC_KTILES 48            // 48 x 32 = 1536
#define FC_KC 32                // k per mainloop iter
#define FC_STAGES 4
#define FC_ROWB 80              // padded smem row bytes (32 bf16 = 64B data + 16B pad)
#define FC_A_STAGE (128 * FC_ROWB)              // 10240
#define FC_B_STAGE (256 * FC_ROWB)              // 20480
#define FC_STAGE_BYTES (FC_A_STAGE + FC_B_STAGE)
#define FC_SMEM (FC_STAGES * FC_STAGE_BYTES)    // 122880 (epilogue aliases this)

// ---------------- scratch (device globals; no allocation allowed) -----------
__device__ float g_emb[BS * D_];
__device__ float g_pre[BS * 2048];
__device__ float g_out[BS * K2H];
__device__ float g_h[2][B_ * H_];
__device__ __nv_bfloat16 g_a2[BS * 1536];            // [2048,1536] = [A_hi|A_hi|A_lo]
__device__ __nv_bfloat16 g_w2[(size_t)V_ * 1024];    // [32000,1024] = [W_hi|W_lo]
__device__ int   g_is64;
__device__ int          g_cnt;
__device__ volatile int g_flag;

// ---------------- helpers ---------------------------------------------------
__device__ __forceinline__ float sigf(float x) { return 1.0f / (1.0f + expf(-x)); }

__device__ __forceinline__ uint32_t smem_u32(const void* p) {
    uint32_t a;
    asm("{ .reg .u64 t; cvta.to.shared.u64 t, %1; cvt.u32.u64 %0, t; }" : "=r"(a) : "l"(p));
    return a;
}
__device__ __forceinline__ void cp_async16(uint32_t s, const void* g) {
    asm volatile("cp.async.cg.shared.global [%0], [%1], 16;" :: "r"(s), "l"(g));
}
#define CP_COMMIT() asm volatile("cp.async.commit_group;" ::: "memory")
#define CP_WAIT(n)  asm volatile("cp.async.wait_group %0;" :: "n"(n) : "memory")

__device__ __forceinline__ void ldsm_x4(uint32_t* r, uint32_t addr) {
    asm volatile("ldmatrix.sync.aligned.m8n8.x4.shared.b16 {%0,%1,%2,%3}, [%4];"
                 : "=r"(r[0]), "=r"(r[1]), "=r"(r[2]), "=r"(r[3]) : "r"(addr));
}
__device__ __forceinline__ void mma16816(float* c, const uint32_t* a,
                                         uint32_t b0, uint32_t b1) {
    asm volatile(
        "mma.sync.aligned.m16n8k16.row.col.f32.bf16.bf16.f32 "
        "{%0,%1,%2,%3}, {%4,%5,%6,%7}, {%8,%9}, {%0,%1,%2,%3};"
        : "+f"(c[0]), "+f"(c[1]), "+f"(c[2]), "+f"(c[3])
        : "r"(a[0]), "r"(a[1]), "r"(a[2]), "r"(a[3]), "r"(b0), "r"(b1));
}

// ---------------- dtype detect: int64 tokens have zero high words -----------
__global__ void detect_kernel(const int* __restrict__ xi) {
    __shared__ int red[256];
    int acc = 0;
    for (int i = threadIdx.x; i < 1024; i += 256) acc |= xi[2 * i + 1];
    red[threadIdx.x] = acc;
    __syncthreads();
    for (int s = 128; s > 0; s >>= 1) {
        if (threadIdx.x < s) red[threadIdx.x] |= red[threadIdx.x + s];
        __syncthreads();
    }
    if (threadIdx.x == 0) g_is64 = (red[0] == 0) ? 1 : 0;
}

// ---------------- per-launch state init (replay-deterministic) --------------
__global__ void zero_state() {
    int i = blockIdx.x * 256 + threadIdx.x;
    if (i < B_ * H_) g_h[0][i] = 0.0f;
    if (i == 0) { g_cnt = 0; g_flag = 0; }
}

// ---------------- embedding gather ------------------------------------------
__global__ void gather_kernel(const int* __restrict__ xi,
                              const float4* __restrict__ emb4) {
    int idx = blockIdx.x * 256 + threadIdx.x;
    int r = idx >> 6, c = idx & 63;
    long long tok;
    if (g_is64) tok = ((const long long*)xi)[r];
    else        tok = (long long)xi[r];
    ((float4*)g_emb)[r * 64 + c] = emb4[(size_t)tok * 64 + c];
}

// ---------------- input projection GEMM: [2048,256] x [2048,256]^T ----------
__global__ __launch_bounds__(256, 2)
void proj_gemm(const float* __restrict__ wf, const float* __restrict__ wb,
               const float* __restrict__ bif, const float* __restrict__ bhf,
               const float* __restrict__ bib, const float* __restrict__ bhb) {
    __shared__ float As[16][132];
    __shared__ float Bs[16][132];
    int m0 = blockIdx.y * 128, n0 = blockIdx.x * 128;
    const float *Bw, *bb1, *bb2;
    if (n0 < 1024) { Bw = wf + (size_t)n0 * 256;          bb1 = bif + n0;          bb2 = bhf + n0; }
    else           { Bw = wb + (size_t)(n0 - 1024) * 256; bb1 = bib + (n0 - 1024); bb2 = bhb + (n0 - 1024); }

    int tid = threadIdx.x;
    int tm = (tid >> 4) << 3, tn = (tid & 15) << 3;
    float acc[8][8] = {};

    for (int k0 = 0; k0 < 256; k0 += 16) {
#pragma unroll
        for (int i = 0; i < 2; i++) {
            int q = tid + i * 256;
            int row = q >> 2, qc = q & 3;
            float4 va = *(const float4*)(g_emb + (size_t)(m0 + row) * 256 + k0 + qc * 4);
            float4 vb = *(const float4*)(Bw + (size_t)row * 256 + k0 + qc * 4);
            As[qc * 4 + 0][row] = va.x; As[qc * 4 + 1][row] = va.y;
            As[qc * 4 + 2][row] = va.z; As[qc * 4 + 3][row] = va.w;
            Bs[qc * 4 + 0][row] = vb.x; Bs[qc * 4 + 1][row] = vb.y;
            Bs[qc * 4 + 2][row] = vb.z; Bs[qc * 4 + 3][row] = vb.w;
        }
        __syncthreads();
#pragma unroll
        for (int k = 0; k < 16; k++) {
            float a[8], b[8];
            *(float4*)(a)     = *(const float4*)&As[k][tm];
            *(float4*)(a + 4) = *(const float4*)&As[k][tm + 4];
            *(float4*)(b)     = *(const float4*)&Bs[k][tn];
            *(float4*)(b + 4) = *(const float4*)&Bs[k][tn + 4];
#pragma unroll
            for (int ii = 0; ii < 8; ii++)
#pragma unroll
                for (int jj = 0; jj < 8; jj++) acc[ii][jj] += a[ii] * b[jj];
        }
        __syncthreads();
    }
#pragma unroll
    for (int ii = 0; ii < 8; ii++) {
        int r = m0 + tm + ii;
#pragma unroll
        for (int jj = 0; jj < 8; jj += 4) {
            float4 o;
            o.x = acc[ii][jj + 0] + bb1[tn + jj + 0] + bb2[tn + jj + 0];
            o.y = acc[ii][jj + 1] + bb1[tn + jj + 1] + bb2[tn + jj + 1];
            o.z = acc[ii][jj + 2] + bb1[tn + jj + 2] + bb2[tn + jj + 2];
            o.w = acc[ii][jj + 3] + bb1[tn + jj + 3] + bb2[tn + jj + 3];
            *(float4*)(g_pre + (size_t)r * 2048 + n0 + tn + jj) = o;
        }
    }
}

// ---------------- backward direction: single cell step from zero state ------
__global__ void hb_kernel() {
    int idx = blockIdx.x * 256 + threadIdx.x;
    int r = idx >> 8, j = idx & 255;
    const float* p = g_pre + (size_t)r * 2048 + 1024;
    float ig = sigf(p[j]);
    float gg = tanhf(p[512 + j]);
    float og = sigf(p[768 + j]);
    g_out[(size_t)r * K2H + 256 + j] = og * tanhf(ig * gg);
}

// ---------------- forward LSTM: single persistent kernel --------------------
__global__ __launch_bounds__(256, 1)
void lstm_persist(const float* __restrict__ w_hh) {
    __shared__ float sw[16][260];
    __shared__ float sh[16][260];
    __shared__ float spre[4][16][4];
    __shared__ int sense;
    int tid = threadIdx.x;
    int j0 = blockIdx.x * 4;
    if (tid == 0) sense = 0;

#pragma unroll
    for (int i = 0; i < 4; i++) {
        int q = tid + i * 256;
        int rr = q >> 6, kc = q & 63;
        int gi = rr >> 2, jj = rr & 3;
        int grow = gi * 256 + j0 + jj;
        float4 wv = ((const float4*)w_hh)[grow * 64 + kc];
        *(float4*)&sw[rr][kc * 4] = wv;
    }

    float creg = 0.0f;

    for (int t = 0; t < S_; t++) {
        const float4* __restrict__ h_in = (const float4*)g_h[t & 1];
        float* h_out = g_h[(t + 1) & 1];

#pragma unroll
        for (int i = 0; i < 4; i++) {
            int q = tid + i * 256;
            int rr = q >> 6, kc = q & 63;
            float4 hv = __ldcg(h_in + rr * 64 + kc);
            *(float4*)&sh[rr][kc * 4] = hv;
        }
        __syncthreads();

        {
            int b = tid >> 4, rr = tid & 15;
            int gi = rr >> 2, jj = rr & 3;
            const float4* wr = (const float4*)&sw[rr][0];
            const float4* hr = (const float4*)&sh[b][0];
            float acc = 0.0f;
#pragma unroll 16
            for (int kc = 0; kc < 64; kc++) {
                float4 w = wr[kc], h = hr[kc];
                acc += w.x * h.x + w.y * h.y + w.z * h.z + w.w * h.w;
            }
            int r = b * S_ + t;
            acc += g_pre[(size_t)r * 2048 + gi * 256 + j0 + jj];
            spre[gi][b][jj] = acc;
        }
        __syncthreads();

        if (tid < 64) {
            int b = tid >> 2, jj = tid & 3;
            int j = j0 + jj;
            float ig = sigf(spre[0][b][jj]);
            float fg = sigf(spre[1][b][jj]);
            float gg = tanhf(spre[2][b][jj]);
            float og = sigf(spre[3][b][jj]);
            creg = fg * creg + ig * gg;
            float h = og * tanhf(creg);
            h_out[b * 256 + j] = h;
            g_out[(size_t)(b * S_ + t) * K2H + j] = h;
            __threadfence();
        }

        __syncthreads();
        if (tid == 0) {
            int s = sense ^ 1;
            sense = s;
            int v = atomicAdd(&g_cnt, 1);
            if (v == NCTA_LSTM - 1) {
                g_cnt = 0;
                __threadfence();
                g_flag = s;
            } else {
                while (g_flag != s) __nanosleep(32);
            }
            __threadfence();
        }
        __syncthreads();
    }
}

// ---------------- fp32 -> bf16 hi/lo conversions -----------------------------
__global__ void convA() {
    int idx = blockIdx.x * 256 + threadIdx.x;
    int r = idx >> 8, kp = idx & 255;
    float2 v = *(const float2*)(g_out + (size_t)r * 512 + kp * 2);
    __nv_bfloat16 h0 = __float2bfloat16(v.x), h1 = __float2bfloat16(v.y);
    __nv_bfloat16 l0 = __float2bfloat16(v.x - __bfloat162float(h0));
    __nv_bfloat16 l1 = __float2bfloat16(v.y - __bfloat162float(h1));
    __nv_bfloat162 hp; hp.x = h0; hp.y = h1;
    __nv_bfloat162 lp; lp.x = l0; lp.y = l1;
    __nv_bfloat162* o = (__nv_bfloat162*)(g_a2 + (size_t)r * 1536);
    o[kp] = hp; o[256 + kp] = hp; o[512 + kp] = lp;
}

__global__ void convW(const float* __restrict__ W) {
    size_t idx = (size_t)blockIdx.x * 256 + threadIdx.x;
    size_t r = idx >> 8; int kp = (int)(idx & 255);
    float2 v = *(const float2*)(W + r * 512 + kp * 2);
    __nv_bfloat16 h0 = __float2bfloat16(v.x), h1 = __float2bfloat16(v.y);
    __nv_bfloat16 l0 = __float2bfloat16(v.x - __bfloat162float(h0));
    __nv_bfloat16 l1 = __float2bfloat16(v.y - __bfloat162float(h1));
    __nv_bfloat162 hp; hp.x = h0; hp.y = h1;
    __nv_bfloat162 lp; lp.x = l0; lp.y = l1;
    __nv_bfloat162* o = (__nv_bfloat162*)(g_w2 + r * 1024);
    o[kp] = hp; o[256 + kp] = lp;
}

// ---------------- FC GEMM via mma.sync (HMMA bf16) ---------------------------
// CTA 128x256, 8 warps (2m x 4n), warp tile 64x64, 4-stage cp.async, KC=32.
static __device__ __forceinline__
void fc_load_stage(uint32_t sbase, int tid, int m0, int n0, int kt) {
    int slot = kt & 3;
    uint32_t sa = sbase + slot * FC_STAGE_BYTES;
    uint32_t sb = sa + FC_A_STAGE;
    int ke = kt * FC_KC;
    int kB = (ke < 1024) ? ke : ke - 1024;           // seg3 re-reads W_hi
    const __nv_bfloat16* ag = g_a2 + (size_t)m0 * 1536 + ke;
    const __nv_bfloat16* bg = g_w2 + (size_t)n0 * 1024 + kB;
    // A: 128 rows x 4 chunks = 512
#pragma unroll
    for (int i = 0; i < 2; i++) {
        int ch = tid + i * 256;
        int r = ch >> 2, c = ch & 3;
        cp_async16(sa + r * FC_ROWB + c * 16, ag + (size_t)r * 1536 + c * 8);
    }
    // B: 256 rows x 4 chunks = 1024
#pragma unroll
    for (int i = 0; i < 4; i++) {
        int ch = tid + i * 256;
        int r = ch >> 2, c = ch & 3;
        cp_async16(sb + r * FC_ROWB + c * 16, bg + (size_t)r * 1024 + c * 8);
    }
}

__global__ __launch_bounds__(256, 1)
void fc_gemm_mma(const float* __restrict__ bias, float* __restrict__ C) {
    extern __shared__ char smem[];
    uint32_t sbase = smem_u32(smem);
    int tid = threadIdx.x, wid = tid >> 5, lane = tid & 31;
    int m0 = blockIdx.x * 128;                       // 16 tiles (fastest -> W L2 reuse)
    int n0 = blockIdx.y * 256;                       // 125 tiles
    int wm = (wid >> 2) * 64;                        // warp m base (0/64)
    int wn = (wid & 3) * 64;                         // warp n base (0..192)

    float acc[4][8][4];
#pragma unroll
    for (int a = 0; a < 4; a++)
#pragma unroll
        for (int b = 0; b < 8; b++)
#pragma unroll
            for (int r = 0; r < 4; r++) acc[a][b][r] = 0.0f;

    // per-lane ldmatrix base offsets within a stage
    uint32_t aOff = (uint32_t)(wm + (lane & 15)) * FC_ROWB + (uint32_t)(lane >> 4) * 16;
    int bn = (lane & 7) + ((lane >> 4) & 1) * 8;
    uint32_t bOff = (uint32_t)(wn + bn) * FC_ROWB + (uint32_t)((lane >> 3) & 1) * 16;

    // prologue: stages 0..2
    fc_load_stage(sbase, tid, m0, n0, 0); CP_COMMIT();
    fc_load_stage(sbase, tid, m0, n0, 1); CP_COMMIT();
    fc_load_stage(sbase, tid, m0, n0, 2); CP_COMMIT();

#pragma unroll 1
    for (int kt = 0; kt < FC_KTILES; kt++) {
        CP_WAIT(2);
        __syncthreads();          // orders slot reuse for the load below too
        if (kt + 3 < FC_KTILES) fc_load_stage(sbase, tid, m0, n0, kt + 3);
        CP_COMMIT();              // empty-commit keeps group count in step

        int slot = kt & 3;
        uint32_t aS = sbase + slot * FC_STAGE_BYTES;
        uint32_t bS = aS + FC_A_STAGE;
#pragma unroll
        for (int ks = 0; ks < 2; ks++) {
            uint32_t k2 = (uint32_t)(ks * 32);       // 16 bf16 = 32 bytes
            uint32_t af[4][4];
#pragma unroll
            for (int mb = 0; mb < 4; mb++)
                ldsm_x4(af[mb], aS + aOff + (uint32_t)mb * 16 * FC_ROWB + k2);
            uint32_t bfr[4][4];
#pragma unroll
            for (int nq = 0; nq < 4; nq++)
                ldsm_x4(bfr[nq], bS + bOff + (uint32_t)nq * 16 * FC_ROWB + k2);
#pragma unroll
            for (int mb = 0; mb < 4; mb++)
#pragma unroll
                for (int nb = 0; nb < 8; nb++)
                    mma16816(acc[mb][nb], af[mb],
                             bfr[nb >> 1][(nb & 1) * 2], bfr[nb >> 1][(nb & 1) * 2 + 1]);
        }
    }

    // epilogue: two 128-col passes staged through smem (aliases pipeline bufs)
    float* epi = (float*)smem;                        // [128][132]
    int er = lane >> 2, ec = (lane & 3) * 2;
#pragma unroll 1
    for (int h = 0; h < 2; h++) {
        __syncthreads();
        if (((wid & 3) >> 1) == h) {
            int nbase = wn - h * 128;                 // 0 or 64 within this pass
#pragma unroll
            for (int mb = 0; mb < 4; mb++) {
#pragma unroll
                for (int nb = 0; nb < 8; nb++) {
                    int m = wm + mb * 16 + er;
                    int n = nbase + nb * 8 + ec;
                    *(float2*)&epi[m * 132 + n]       = make_float2(acc[mb][nb][0], acc[mb][nb][1]);
                    *(float2*)&epi[(m + 8) * 132 + n] = make_float2(acc[mb][nb][2], acc[mb][nb][3]);
                }
            }
        }
        __syncthreads();
        float4 bv = *(const float4*)(bias + n0 + h * 128 + lane * 4);
#pragma unroll 1
        for (int r = 0; r < 16; r++) {
            int m = wid * 16 + r;
            float4 v = *(float4*)&epi[m * 132 + lane * 4];
            v.x += bv.x; v.y += bv.y; v.z += bv.z; v.w += bv.w;
            *(float4*)&C[(size_t)(m0 + m) * V_ + n0 + h * 128 + lane * 4] = v;
        }
    }
}

// ---------------- launch ----------------------------------------------------
extern "C" void kernel_launch(void* const* d_in, const int* in_sizes, int n_in,
                              void* d_out, int out_size) {
    const int*   x      = (const int*)d_in[0];
    const float* embed  = (const float*)d_in[1];
    const float* w_ih_f = (const float*)d_in[2];
    const float* w_hh_f = (const float*)d_in[3];
    const float* b_ih_f = (const float*)d_in[4];
    const float* b_hh_f = (const float*)d_in[5];
    const float* w_ih_b = (const float*)d_in[6];
    // d_in[7] = w_hh_b : multiplied by the zero initial state -> unused
    const float* b_ih_b = (const float*)d_in[8];
    const float* b_hh_b = (const float*)d_in[9];
    const float* fc_w   = (const float*)d_in[10];
    const float* fc_b   = (const float*)d_in[11];
    float* out = (float*)d_out;

    cudaFuncSetAttribute(fc_gemm_mma, cudaFuncAttributeMaxDynamicSharedMemorySize, FC_SMEM);

    detect_kernel<<<1, 256>>>(x);
    zero_state<<<16, 256>>>();
    gather_kernel<<<512, 256>>>(x, (const float4*)embed);
    convW<<<V_ * 512 / 2 / 256, 256>>>(fc_w);
    proj_gemm<<<dim3(16, 16), 256>>>(w_ih_f, w_ih_b, b_ih_f, b_hh_f, b_ih_b, b_hh_b);
    hb_kernel<<<2048, 256>>>();
    lstm_persist<<<NCTA_LSTM, 256>>>(w_hh_f);
    convA<<<2048, 256>>>();
    fc_gemm_mma<<<dim3(16, 125), 256, FC_SMEM>>>(fc_b, out);
    (void)in_sizes; (void)n_in; (void)out_size;
}

// round 9
// speedup vs baseline: 1.7164x; 1.1850x over previous
#include <cuda_runtime.h>
#include <cuda_fp16.h>
#include <cstdint>
#include <math.h>

// Problem dims
#define B_  16
#define S_  128
#define BS  2048      // B*S
#define D_  256
#define H_  256
#define V_  32000
#define K2H 512       // 2*H
#define NCTA_LSTM 64

// FC GEMM (mma.sync fp16): C[2048,32000] = A2[2048,1024] x W2eff[32000,1024]^T
// A2 = [A_hi | A_lo] (fp16 split of A, exact to ~2^-22); W2 = W_hi = f16(W).
// Both K-segments of B read the SAME W_hi region: C = (A_hi + A_lo) . W_hi.
// Dropped error = A . W_lo ~ 2e-4 relative (budget 1e-3).
// CTA tile 128(M) x 256(N), 8 warps (2m x 4n), warp tile 64x64.
#define FC_KTILES 32            // 32 x 32 = 1024
#define FC_KC 32                // k per mainloop iter
#define FC_STAGES 4
#define FC_ROWB 80              // padded smem row bytes (32 f16 = 64B data + 16B pad)
#define FC_A_STAGE (128 * FC_ROWB)              // 10240
#define FC_B_STAGE (256 * FC_ROWB)              // 20480
#define FC_STAGE_BYTES (FC_A_STAGE + FC_B_STAGE)
#define FC_SMEM (FC_STAGES * FC_STAGE_BYTES)    // 122880 (epilogue aliases this)

// ---------------- scratch (device globals; no allocation allowed) -----------
__device__ float g_emb[BS * D_];
__device__ float g_pre[BS * 2048];
__device__ float g_out[BS * K2H];
__device__ float g_h[2][B_ * H_];
__device__ __half g_a2[BS * 1024];               // [2048,1024] = [A_hi|A_lo]
__device__ __half g_w2[(size_t)V_ * 512];        // [32000,512] = W_hi
__device__ int   g_is64;
__device__ int          g_cnt;
__device__ volatile int g_flag;

// ---------------- helpers ---------------------------------------------------
__device__ __forceinline__ float sigf(float x) { return 1.0f / (1.0f + expf(-x)); }

__device__ __forceinline__ uint32_t smem_u32(const void* p) {
    uint32_t a;
    asm("{ .reg .u64 t; cvta.to.shared.u64 t, %1; cvt.u32.u64 %0, t; }" : "=r"(a) : "l"(p));
    return a;
}
__device__ __forceinline__ void cp_async16(uint32_t s, const void* g) {
    asm volatile("cp.async.cg.shared.global [%0], [%1], 16;" :: "r"(s), "l"(g));
}
#define CP_COMMIT() asm volatile("cp.async.commit_group;" ::: "memory")
#define CP_WAIT(n)  asm volatile("cp.async.wait_group %0;" :: "n"(n) : "memory")

__device__ __forceinline__ void ldsm_x4(uint32_t* r, uint32_t addr) {
    asm volatile("ldmatrix.sync.aligned.m8n8.x4.shared.b16 {%0,%1,%2,%3}, [%4];"
                 : "=r"(r[0]), "=r"(r[1]), "=r"(r[2]), "=r"(r[3]) : "r"(addr));
}
__device__ __forceinline__ void mma16816(float* c, const uint32_t* a,
                                         uint32_t b0, uint32_t b1) {
    asm volatile(
        "mma.sync.aligned.m16n8k16.row.col.f32.f16.f16.f32 "
        "{%0,%1,%2,%3}, {%4,%5,%6,%7}, {%8,%9}, {%0,%1,%2,%3};"
        : "+f"(c[0]), "+f"(c[1]), "+f"(c[2]), "+f"(c[3])
        : "r"(a[0]), "r"(a[1]), "r"(a[2]), "r"(a[3]), "r"(b0), "r"(b1));
}

// ---------------- dtype detect: int64 tokens have zero high words -----------
__global__ void detect_kernel(const int* __restrict__ xi) {
    __shared__ int red[256];
    int acc = 0;
    for (int i = threadIdx.x; i < 1024; i += 256) acc |= xi[2 * i + 1];
    red[threadIdx.x] = acc;
    __syncthreads();
    for (int s = 128; s > 0; s >>= 1) {
        if (threadIdx.x < s) red[threadIdx.x] |= red[threadIdx.x + s];
        __syncthreads();
    }
    if (threadIdx.x == 0) g_is64 = (red[0] == 0) ? 1 : 0;
}

// ---------------- per-launch state init (replay-deterministic) --------------
__global__ void zero_state() {
    int i = blockIdx.x * 256 + threadIdx.x;
    if (i < B_ * H_) g_h[0][i] = 0.0f;
    if (i == 0) { g_cnt = 0; g_flag = 0; }
}

// ---------------- embedding gather ------------------------------------------
__global__ void gather_kernel(const int* __restrict__ xi,
                              const float4* __restrict__ emb4) {
    int idx = blockIdx.x * 256 + threadIdx.x;
    int r = idx >> 6, c = idx & 63;
    long long tok;
    if (g_is64) tok = ((const long long*)xi)[r];
    else        tok = (long long)xi[r];
    ((float4*)g_emb)[r * 64 + c] = emb4[(size_t)tok * 64 + c];
}

// ---------------- input projection GEMM: [2048,256] x [2048,256]^T ----------
__global__ __launch_bounds__(256, 2)
void proj_gemm(const float* __restrict__ wf, const float* __restrict__ wb,
               const float* __restrict__ bif, const float* __restrict__ bhf,
               const float* __restrict__ bib, const float* __restrict__ bhb) {
    __shared__ float As[16][132];
    __shared__ float Bs[16][132];
    int m0 = blockIdx.y * 128, n0 = blockIdx.x * 128;
    const float *Bw, *bb1, *bb2;
    if (n0 < 1024) { Bw = wf + (size_t)n0 * 256;          bb1 = bif + n0;          bb2 = bhf + n0; }
    else           { Bw = wb + (size_t)(n0 - 1024) * 256; bb1 = bib + (n0 - 1024); bb2 = bhb + (n0 - 1024); }

    int tid = threadIdx.x;
    int tm = (tid >> 4) << 3, tn = (tid & 15) << 3;
    float acc[8][8] = {};

    for (int k0 = 0; k0 < 256; k0 += 16) {
#pragma unroll
        for (int i = 0; i < 2; i++) {
            int q = tid + i * 256;
            int row = q >> 2, qc = q & 3;
            float4 va = *(const float4*)(g_emb + (size_t)(m0 + row) * 256 + k0 + qc * 4);
            float4 vb = *(const float4*)(Bw + (size_t)row * 256 + k0 + qc * 4);
            As[qc * 4 + 0][row] = va.x; As[qc * 4 + 1][row] = va.y;
            As[qc * 4 + 2][row] = va.z; As[qc * 4 + 3][row] = va.w;
            Bs[qc * 4 + 0][row] = vb.x; Bs[qc * 4 + 1][row] = vb.y;
            Bs[qc * 4 + 2][row] = vb.z; Bs[qc * 4 + 3][row] = vb.w;
        }
        __syncthreads();
#pragma unroll
        for (int k = 0; k < 16; k++) {
            float a[8], b[8];
            *(float4*)(a)     = *(const float4*)&As[k][tm];
            *(float4*)(a + 4) = *(const float4*)&As[k][tm + 4];
            *(float4*)(b)     = *(const float4*)&Bs[k][tn];
            *(float4*)(b + 4) = *(const float4*)&Bs[k][tn + 4];
#pragma unroll
            for (int ii = 0; ii < 8; ii++)
#pragma unroll
                for (int jj = 0; jj < 8; jj++) acc[ii][jj] += a[ii] * b[jj];
        }
        __syncthreads();
    }
#pragma unroll
    for (int ii = 0; ii < 8; ii++) {
        int r = m0 + tm + ii;
#pragma unroll
        for (int jj = 0; jj < 8; jj += 4) {
            float4 o;
            o.x = acc[ii][jj + 0] + bb1[tn + jj + 0] + bb2[tn + jj + 0];
            o.y = acc[ii][jj + 1] + bb1[tn + jj + 1] + bb2[tn + jj + 1];
            o.z = acc[ii][jj + 2] + bb1[tn + jj + 2] + bb2[tn + jj + 2];
            o.w = acc[ii][jj + 3] + bb1[tn + jj + 3] + bb2[tn + jj + 3];
            *(float4*)(g_pre + (size_t)r * 2048 + n0 + tn + jj) = o;
        }
    }
}

// ---------------- backward direction: single cell step from zero state ------
__global__ void hb_kernel() {
    int idx = blockIdx.x * 256 + threadIdx.x;
    int r = idx >> 8, j = idx & 255;
    const float* p = g_pre + (size_t)r * 2048 + 1024;
    float ig = sigf(p[j]);
    float gg = tanhf(p[512 + j]);
    float og = sigf(p[768 + j]);
    g_out[(size_t)r * K2H + 256 + j] = og * tanhf(ig * gg);
}

// ---------------- forward LSTM: single persistent kernel --------------------
__global__ __launch_bounds__(256, 1)
void lstm_persist(const float* __restrict__ w_hh) {
    __shared__ float sw[16][260];
    __shared__ float sh[16][260];
    __shared__ float spre[4][16][4];
    __shared__ int sense;
    int tid = threadIdx.x;
    int j0 = blockIdx.x * 4;
    if (tid == 0) sense = 0;

#pragma unroll
    for (int i = 0; i < 4; i++) {
        int q = tid + i * 256;
        int rr = q >> 6, kc = q & 63;
        int gi = rr >> 2, jj = rr & 3;
        int grow = gi * 256 + j0 + jj;
        float4 wv = ((const float4*)w_hh)[grow * 64 + kc];
        *(float4*)&sw[rr][kc * 4] = wv;
    }

    float creg = 0.0f;

    for (int t = 0; t < S_; t++) {
        const float4* __restrict__ h_in = (const float4*)g_h[t & 1];
        float* h_out = g_h[(t + 1) & 1];

#pragma unroll
        for (int i = 0; i < 4; i++) {
            int q = tid + i * 256;
            int rr = q >> 6, kc = q & 63;
            float4 hv = __ldcg(h_in + rr * 64 + kc);
            *(float4*)&sh[rr][kc * 4] = hv;
        }
        __syncthreads();

        {
            int b = tid >> 4, rr = tid & 15;
            int gi = rr >> 2, jj = rr & 3;
            const float4* wr = (const float4*)&sw[rr][0];
            const float4* hr = (const float4*)&sh[b][0];
            float acc = 0.0f;
#pragma unroll 16
            for (int kc = 0; kc < 64; kc++) {
                float4 w = wr[kc], h = hr[kc];
                acc += w.x * h.x + w.y * h.y + w.z * h.z + w.w * h.w;
            }
            int r = b * S_ + t;
            acc += g_pre[(size_t)r * 2048 + gi * 256 + j0 + jj];
            spre[gi][b][jj] = acc;
        }
        __syncthreads();

        if (tid < 64) {
            int b = tid >> 2, jj = tid & 3;
            int j = j0 + jj;
            float ig = sigf(spre[0][b][jj]);
            float fg = sigf(spre[1][b][jj]);
            float gg = tanhf(spre[2][b][jj]);
            float og = sigf(spre[3][b][jj]);
            creg = fg * creg + ig * gg;
            float h = og * tanhf(creg);
            h_out[b * 256 + j] = h;
            g_out[(size_t)(b * S_ + t) * K2H + j] = h;
            __threadfence();
        }

        __syncthreads();
        if (tid == 0) {
            int s = sense ^ 1;
            sense = s;
            int v = atomicAdd(&g_cnt, 1);
            if (v == NCTA_LSTM - 1) {
                g_cnt = 0;
                __threadfence();
                g_flag = s;
            } else {
                while (g_flag != s) __nanosleep(32);
            }
            __threadfence();
        }
        __syncthreads();
    }
}

// ---------------- fp32 -> fp16 hi/lo (A) and fp16 hi (W) conversions --------
__global__ void convA() {
    int idx = blockIdx.x * 256 + threadIdx.x;        // 2048 rows x 256 float2
    int r = idx >> 8, kp = idx & 255;
    float2 v = *(const float2*)(g_out + (size_t)r * 512 + kp * 2);
    __half h0 = __float2half_rn(v.x), h1 = __float2half_rn(v.y);
    __half l0 = __float2half_rn(v.x - __half2float(h0));
    __half l1 = __float2half_rn(v.y - __half2float(h1));
    __half2* o = (__half2*)(g_a2 + (size_t)r * 1024);
    o[kp]       = __halves2half2(h0, h1);
    o[256 + kp] = __halves2half2(l0, l1);
}

__global__ void convW(const float* __restrict__ W) {
    size_t idx = (size_t)blockIdx.x * 256 + threadIdx.x;   // 32000 x 256 float2
    size_t r = idx >> 8; int kp = (int)(idx & 255);
    float2 v = *(const float2*)(W + r * 512 + kp * 2);
    __half2* o = (__half2*)(g_w2 + r * 512);
    o[kp] = __halves2half2(__float2half_rn(v.x), __float2half_rn(v.y));
}

// ---------------- FC GEMM via mma.sync (fp16) --------------------------------
// CTA 128x256, 8 warps (2m x 4n), warp tile 64x64, 4-stage cp.async, KC=32.
static __device__ __forceinline__
void fc_load_stage(uint32_t sbase, int tid, int m0, int n0, int kt) {
    int slot = kt & 3;
    uint32_t sa = sbase + slot * FC_STAGE_BYTES;
    uint32_t sb = sa + FC_A_STAGE;
    int ke = kt * FC_KC;
    int kB = ke & 511;                               // both segments read W_hi
    const __half* ag = g_a2 + (size_t)m0 * 1024 + ke;
    const __half* bg = g_w2 + (size_t)n0 * 512 + kB;
    // A: 128 rows x 4 chunks = 512
#pragma unroll
    for (int i = 0; i < 2; i++) {
        int ch = tid + i * 256;
        int r = ch >> 2, c = ch & 3;
        cp_async16(sa + r * FC_ROWB + c * 16, ag + (size_t)r * 1024 + c * 8);
    }
    // B: 256 rows x 4 chunks = 1024
#pragma unroll
    for (int i = 0; i < 4; i++) {
        int ch = tid + i * 256;
        int r = ch >> 2, c = ch & 3;
        cp_async16(sb + r * FC_ROWB + c * 16, bg + (size_t)r * 512 + c * 8);
    }
}

__global__ __launch_bounds__(256, 1)
void fc_gemm_mma(const float* __restrict__ bias, float* __restrict__ C) {
    extern __shared__ char smem[];
    uint32_t sbase = smem_u32(smem);
    int tid = threadIdx.x, wid = tid >> 5, lane = tid & 31;
    int m0 = blockIdx.x * 128;                       // 16 tiles (fastest -> W L2 reuse)
    int n0 = blockIdx.y * 256;                       // 125 tiles
    int wm = (wid >> 2) * 64;                        // warp m base (0/64)
    int wn = (wid & 3) * 64;                         // warp n base (0..192)

    float acc[4][8][4];
#pragma unroll
    for (int a = 0; a < 4; a++)
#pragma unroll
        for (int b = 0; b < 8; b++)
#pragma unroll
            for (int r = 0; r < 4; r++) acc[a][b][r] = 0.0f;

    // per-lane ldmatrix base offsets within a stage
    uint32_t aOff = (uint32_t)(wm + (lane & 15)) * FC_ROWB + (uint32_t)(lane >> 4) * 16;
    int bn = (lane & 7) + ((lane >> 4) & 1) * 8;
    uint32_t bOff = (uint32_t)(wn + bn) * FC_ROWB + (uint32_t)((lane >> 3) & 1) * 16;

    // prologue: stages 0..2
    fc_load_stage(sbase, tid, m0, n0, 0); CP_COMMIT();
    fc_load_stage(sbase, tid, m0, n0, 1); CP_COMMIT();
    fc_load_stage(sbase, tid, m0, n0, 2); CP_COMMIT();

#pragma unroll 1
    for (int kt = 0; kt < FC_KTILES; kt++) {
        CP_WAIT(2);
        __syncthreads();          // orders slot reuse for the load below too
        if (kt + 3 < FC_KTILES) fc_load_stage(sbase, tid, m0, n0, kt + 3);
        CP_COMMIT();              // empty-commit keeps group count in step

        int slot = kt & 3;
        uint32_t aS = sbase + slot * FC_STAGE_BYTES;
        uint32_t bS = aS + FC_A_STAGE;
#pragma unroll
        for (int ks = 0; ks < 2; ks++) {
            uint32_t k2 = (uint32_t)(ks * 32);       // 16 f16 = 32 bytes
            uint32_t af[4][4];
#pragma unroll
            for (int mb = 0; mb < 4; mb++)
                ldsm_x4(af[mb], aS + aOff + (uint32_t)mb * 16 * FC_ROWB + k2);
            uint32_t bfr[4][4];
#pragma unroll
            for (int nq = 0; nq < 4; nq++)
                ldsm_x4(bfr[nq], bS + bOff + (uint32_t)nq * 16 * FC_ROWB + k2);
#pragma unroll
            for (int mb = 0; mb < 4; mb++)
#pragma unroll
                for (int nb = 0; nb < 8; nb++)
                    mma16816(acc[mb][nb], af[mb],
                             bfr[nb >> 1][(nb & 1) * 2], bfr[nb >> 1][(nb & 1) * 2 + 1]);
        }
    }

    // epilogue: two 128-col passes staged through smem (aliases pipeline bufs)
    float* epi = (float*)smem;                        // [128][132]
    int er = lane >> 2, ec = (lane & 3) * 2;
#pragma unroll 1
    for (int h = 0; h < 2; h++) {
        __syncthreads();
        if (((wid & 3) >> 1) == h) {
            int nbase = wn - h * 128;                 // 0 or 64 within this pass
#pragma unroll
            for (int mb = 0; mb < 4; mb++) {
#pragma unroll
                for (int nb = 0; nb < 8; nb++) {
                    int m = wm + mb * 16 + er;
                    int n = nbase + nb * 8 + ec;
                    *(float2*)&epi[m * 132 + n]       = make_float2(acc[mb][nb][0], acc[mb][nb][1]);
                    *(float2*)&epi[(m + 8) * 132 + n] = make_float2(acc[mb][nb][2], acc[mb][nb][3]);
                }
            }
        }
        __syncthreads();
        float4 bv = *(const float4*)(bias + n0 + h * 128 + lane * 4);
#pragma unroll 1
        for (int r = 0; r < 16; r++) {
            int m = wid * 16 + r;
            float4 v = *(float4*)&epi[m * 132 + lane * 4];
            v.x += bv.x; v.y += bv.y; v.z += bv.z; v.w += bv.w;
            *(float4*)&C[(size_t)(m0 + m) * V_ + n0 + h * 128 + lane * 4] = v;
        }
    }
}

// ---------------- launch ----------------------------------------------------
extern "C" void kernel_launch(void* const* d_in, const int* in_sizes, int n_in,
                              void* d_out, int out_size) {
    const int*   x      = (const int*)d_in[0];
    const float* embed  = (const float*)d_in[1];
    const float* w_ih_f = (const float*)d_in[2];
    const float* w_hh_f = (const float*)d_in[3];
    const float* b_ih_f = (const float*)d_in[4];
    const float* b_hh_f = (const float*)d_in[5];
    const float* w_ih_b = (const float*)d_in[6];
    // d_in[7] = w_hh_b : multiplied by the zero initial state -> unused
    const float* b_ih_b = (const float*)d_in[8];
    const float* b_hh_b = (const float*)d_in[9];
    const float* fc_w   = (const float*)d_in[10];
    const float* fc_b   = (const float*)d_in[11];
    float* out = (float*)d_out;

    cudaFuncSetAttribute(fc_gemm_mma, cudaFuncAttributeMaxDynamicSharedMemorySize, FC_SMEM);

    detect_kernel<<<1, 256>>>(x);
    zero_state<<<16, 256>>>();
    gather_kernel<<<512, 256>>>(x, (const float4*)embed);
    convW<<<V_, 256>>>(fc_w);
    proj_gemm<<<dim3(16, 16), 256>>>(w_ih_f, w_ih_b, b_ih_f, b_hh_f, b_ih_b, b_hh_b);
    hb_kernel<<<2048, 256>>>();
    lstm_persist<<<NCTA_LSTM, 256>>>(w_hh_f);
    convA<<<2048, 256>>>();
    fc_gemm_mma<<<dim3(16, 125), 256, FC_SMEM>>>(fc_b, out);
    (void)in_sizes; (void)n_in; (void)out_size;
}

// round 15
// speedup vs baseline: 2.1137x; 1.2315x over previous
#include <cuda_runtime.h>
#include <cuda_fp16.h>
#include <cstdint>
#include <math.h>

// Problem dims
#define B_  16
#define S_  128
#define BS  2048      // B*S
#define D_  256
#define H_  256
#define V_  32000
#define K2H 512       // 2*H
#define NCTA_LSTM 64

// FC GEMM (mma.sync fp16, single-term): C[2048,32000] = f16(A)[2048,512] x f16(W)[32000,512]^T
// Measured anchor: dropping A.W_lo cost 1.19e-4 rel_err; dropping the symmetric
// A_lo.W_hi term adds in quadrature -> predicted ~1.7-2.5e-4 (budget 1e-3).
// CTA tile 128(M) x 256(N), 8 warps (2m x 4n), warp tile 64x64.
#define FC_KTILES 16            // 16 x 32 = 512
#define FC_KC 32                // k per mainloop iter
#define FC_STAGES 4
#define FC_ROWB 80              // padded smem row bytes (32 f16 = 64B data + 16B pad)
#define FC_A_STAGE (128 * FC_ROWB)              // 10240
#define FC_B_STAGE (256 * FC_ROWB)              // 20480
#define FC_STAGE_BYTES (FC_A_STAGE + FC_B_STAGE)
#define FC_SMEM (FC_STAGES * FC_STAGE_BYTES)    // 122880 (epilogue aliases this)

// ---------------- scratch (device globals; no allocation allowed) -----------
__device__ float g_emb[BS * D_];
__device__ float g_pre[BS * 2048];
__device__ float g_out[BS * K2H];
__device__ float g_h[2][B_ * H_];
__device__ __half g_a2[BS * 512];                // [2048,512] = f16(A)
__device__ __half g_w2[(size_t)V_ * 512];        // [32000,512] = f16(W)
__device__ int   g_is64;
__device__ int          g_cnt;
__device__ volatile int g_flag;

// ---------------- helpers ---------------------------------------------------
__device__ __forceinline__ float sigf(float x) { return 1.0f / (1.0f + expf(-x)); }

__device__ __forceinline__ uint32_t smem_u32(const void* p) {
    uint32_t a;
    asm("{ .reg .u64 t; cvta.to.shared.u64 t, %1; cvt.u32.u64 %0, t; }" : "=r"(a) : "l"(p));
    return a;
}
__device__ __forceinline__ void cp_async16(uint32_t s, const void* g) {
    asm volatile("cp.async.cg.shared.global [%0], [%1], 16;" :: "r"(s), "l"(g));
}
#define CP_COMMIT() asm volatile("cp.async.commit_group;" ::: "memory")
#define CP_WAIT(n)  asm volatile("cp.async.wait_group %0;" :: "n"(n) : "memory")

__device__ __forceinline__ void ldsm_x4(uint32_t* r, uint32_t addr) {
    asm volatile("ldmatrix.sync.aligned.m8n8.x4.shared.b16 {%0,%1,%2,%3}, [%4];"
                 : "=r"(r[0]), "=r"(r[1]), "=r"(r[2]), "=r"(r[3]) : "r"(addr));
}
__device__ __forceinline__ void mma16816(float* c, const uint32_t* a,
                                         uint32_t b0, uint32_t b1) {
    asm volatile(
        "mma.sync.aligned.m16n8k16.row.col.f32.f16.f16.f32 "
        "{%0,%1,%2,%3}, {%4,%5,%6,%7}, {%8,%9}, {%0,%1,%2,%3};"
        : "+f"(c[0]), "+f"(c[1]), "+f"(c[2]), "+f"(c[3])
        : "r"(a[0]), "r"(a[1]), "r"(a[2]), "r"(a[3]), "r"(b0), "r"(b1));
}

// ---------------- dtype detect: int64 tokens have zero high words -----------
__global__ void detect_kernel(const int* __restrict__ xi) {
    __shared__ int red[256];
    int acc = 0;
    for (int i = threadIdx.x; i < 1024; i += 256) acc |= xi[2 * i + 1];
    red[threadIdx.x] = acc;
    __syncthreads();
    for (int s = 128; s > 0; s >>= 1) {
        if (threadIdx.x < s) red[threadIdx.x] |= red[threadIdx.x + s];
        __syncthreads();
    }
    if (threadIdx.x == 0) g_is64 = (red[0] == 0) ? 1 : 0;
}

// ---------------- per-launch state init (replay-deterministic) --------------
__global__ void zero_state() {
    int i = blockIdx.x * 256 + threadIdx.x;
    if (i < B_ * H_) g_h[0][i] = 0.0f;
    if (i == 0) { g_cnt = 0; g_flag = 0; }
}

// ---------------- embedding gather ------------------------------------------
__global__ void gather_kernel(const int* __restrict__ xi,
                              const float4* __restrict__ emb4) {
    int idx = blockIdx.x * 256 + threadIdx.x;
    int r = idx >> 6, c = idx & 63;
    long long tok;
    if (g_is64) tok = ((const long long*)xi)[r];
    else        tok = (long long)xi[r];
    ((float4*)g_emb)[r * 64 + c] = emb4[(size_t)tok * 64 + c];
}

// ---------------- input projection GEMM: [2048,256] x [2048,256]^T ----------
__global__ __launch_bounds__(256, 2)
void proj_gemm(const float* __restrict__ wf, const float* __restrict__ wb,
               const float* __restrict__ bif, const float* __restrict__ bhf,
               const float* __restrict__ bib, const float* __restrict__ bhb) {
    __shared__ float As[16][132];
    __shared__ float Bs[16][132];
    int m0 = blockIdx.y * 128, n0 = blockIdx.x * 128;
    const float *Bw, *bb1, *bb2;
    if (n0 < 1024) { Bw = wf + (size_t)n0 * 256;          bb1 = bif + n0;          bb2 = bhf + n0; }
    else           { Bw = wb + (size_t)(n0 - 1024) * 256; bb1 = bib + (n0 - 1024); bb2 = bhb + (n0 - 1024); }

    int tid = threadIdx.x;
    int tm = (tid >> 4) << 3, tn = (tid & 15) << 3;
    float acc[8][8] = {};

    for (int k0 = 0; k0 < 256; k0 += 16) {
#pragma unroll
        for (int i = 0; i < 2; i++) {
            int q = tid + i * 256;
            int row = q >> 2, qc = q & 3;
            float4 va = *(const float4*)(g_emb + (size_t)(m0 + row) * 256 + k0 + qc * 4);
            float4 vb = *(const float4*)(Bw + (size_t)row * 256 + k0 + qc * 4);
            As[qc * 4 + 0][row] = va.x; As[qc * 4 + 1][row] = va.y;
            As[qc * 4 + 2][row] = va.z; As[qc * 4 + 3][row] = va.w;
            Bs[qc * 4 + 0][row] = vb.x; Bs[qc * 4 + 1][row] = vb.y;
            Bs[qc * 4 + 2][row] = vb.z; Bs[qc * 4 + 3][row] = vb.w;
        }
        __syncthreads();
#pragma unroll
        for (int k = 0; k < 16; k++) {
            float a[8], b[8];
            *(float4*)(a)     = *(const float4*)&As[k][tm];
            *(float4*)(a + 4) = *(const float4*)&As[k][tm + 4];
            *(float4*)(b)     = *(const float4*)&Bs[k][tn];
            *(float4*)(b + 4) = *(const float4*)&Bs[k][tn + 4];
#pragma unroll
            for (int ii = 0; ii < 8; ii++)
#pragma unroll
                for (int jj = 0; jj < 8; jj++) acc[ii][jj] += a[ii] * b[jj];
        }
        __syncthreads();
    }
#pragma unroll
    for (int ii = 0; ii < 8; ii++) {
        int r = m0 + tm + ii;
#pragma unroll
        for (int jj = 0; jj < 8; jj += 4) {
            float4 o;
            o.x = acc[ii][jj + 0] + bb1[tn + jj + 0] + bb2[tn + jj + 0];
            o.y = acc[ii][jj + 1] + bb1[tn + jj + 1] + bb2[tn + jj + 1];
            o.z = acc[ii][jj + 2] + bb1[tn + jj + 2] + bb2[tn + jj + 2];
            o.w = acc[ii][jj + 3] + bb1[tn + jj + 3] + bb2[tn + jj + 3];
            *(float4*)(g_pre + (size_t)r * 2048 + n0 + tn + jj) = o;
        }
    }
}

// ---------------- backward direction: single cell step from zero state ------
__global__ void hb_kernel() {
    int idx = blockIdx.x * 256 + threadIdx.x;
    int r = idx >> 8, j = idx & 255;
    const float* p = g_pre + (size_t)r * 2048 + 1024;
    float ig = sigf(p[j]);
    float gg = tanhf(p[512 + j]);
    float og = sigf(p[768 + j]);
    g_out[(size_t)r * K2H + 256 + j] = og * tanhf(ig * gg);
}

// ---------------- forward LSTM: single persistent kernel --------------------
__global__ __launch_bounds__(256, 1)
void lstm_persist(const float* __restrict__ w_hh) {
    __shared__ float sw[16][260];
    __shared__ float sh[16][260];
    __shared__ float spre[4][16][4];
    __shared__ int sense;
    int tid = threadIdx.x;
    int j0 = blockIdx.x * 4;
    if (tid == 0) sense = 0;

#pragma unroll
    for (int i = 0; i < 4; i++) {
        int q = tid + i * 256;
        int rr = q >> 6, kc = q & 63;
        int gi = rr >> 2, jj = rr & 3;
        int grow = gi * 256 + j0 + jj;
        float4 wv = ((const float4*)w_hh)[grow * 64 + kc];
        *(float4*)&sw[rr][kc * 4] = wv;
    }

    float creg = 0.0f;

    for (int t = 0; t < S_; t++) {
        const float4* __restrict__ h_in = (const float4*)g_h[t & 1];
        float* h_out = g_h[(t + 1) & 1];

#pragma unroll
        for (int i = 0; i < 4; i++) {
            int q = tid + i * 256;
            int rr = q >> 6, kc = q & 63;
            float4 hv = __ldcg(h_in + rr * 64 + kc);
            *(float4*)&sh[rr][kc * 4] = hv;
        }
        __syncthreads();

        {
            int b = tid >> 4, rr = tid & 15;
            int gi = rr >> 2, jj = rr & 3;
            const float4* wr = (const float4*)&sw[rr][0];
            const float4* hr = (const float4*)&sh[b][0];
            float acc = 0.0f;
#pragma unroll 16
            for (int kc = 0; kc < 64; kc++) {
                float4 w = wr[kc], h = hr[kc];
                acc += w.x * h.x + w.y * h.y + w.z * h.z + w.w * h.w;
            }
            int r = b * S_ + t;
            acc += g_pre[(size_t)r * 2048 + gi * 256 + j0 + jj];
            spre[gi][b][jj] = acc;
        }
        __syncthreads();

        if (tid < 64) {
            int b = tid >> 2, jj = tid & 3;
            int j = j0 + jj;
            float ig = sigf(spre[0][b][jj]);
            float fg = sigf(spre[1][b][jj]);
            float gg = tanhf(spre[2][b][jj]);
            float og = sigf(spre[3][b][jj]);
            creg = fg * creg + ig * gg;
            float h = og * tanhf(creg);
            h_out[b * 256 + j] = h;
            g_out[(size_t)(b * S_ + t) * K2H + j] = h;
            __threadfence();
        }

        __syncthreads();
        if (tid == 0) {
            int s = sense ^ 1;
            sense = s;
            int v = atomicAdd(&g_cnt, 1);
            if (v == NCTA_LSTM - 1) {
                g_cnt = 0;
                __threadfence();
                g_flag = s;
            } else {
                while (g_flag != s) __nanosleep(32);
            }
            __threadfence();
        }
        __syncthreads();
    }
}

// ---------------- fp32 -> fp16 conversions -----------------------------------
// 2048 rows x 256 half2 items per row = 524288 items -> grid 2048 x 256.
__global__ void convA() {
    int idx = blockIdx.x * 256 + threadIdx.x;
    int r = idx >> 8, kp = idx & 255;
    float2 v = *(const float2*)(g_out + (size_t)r * 512 + kp * 2);
    __half2* o = (__half2*)(g_a2 + (size_t)r * 512);
    o[kp] = __halves2half2(__float2half_rn(v.x), __float2half_rn(v.y));
}

__global__ void convW(const float* __restrict__ W) {
    size_t idx = (size_t)blockIdx.x * 256 + threadIdx.x;   // 32000 x 256 float2
    size_t r = idx >> 8; int kp = (int)(idx & 255);
    float2 v = *(const float2*)(W + r * 512 + kp * 2);
    __half2* o = (__half2*)(g_w2 + r * 512);
    o[kp] = __halves2half2(__float2half_rn(v.x), __float2half_rn(v.y));
}

// ---------------- FC GEMM via mma.sync (fp16, single-term) -------------------
// CTA 128x256, 8 warps (2m x 4n), warp tile 64x64, 4-stage cp.async, KC=32.
static __device__ __forceinline__
void fc_load_stage(uint32_t sbase, int tid, int m0, int n0, int kt) {
    int slot = kt & 3;
    uint32_t sa = sbase + slot * FC_STAGE_BYTES;
    uint32_t sb = sa + FC_A_STAGE;
    int ke = kt * FC_KC;
    const __half* ag = g_a2 + (size_t)m0 * 512 + ke;
    const __half* bg = g_w2 + (size_t)n0 * 512 + ke;
    // A: 128 rows x 4 chunks = 512
#pragma unroll
    for (int i = 0; i < 2; i++) {
        int ch = tid + i * 256;
        int r = ch >> 2, c = ch & 3;
        cp_async16(sa + r * FC_ROWB + c * 16, ag + (size_t)r * 512 + c * 8);
    }
    // B: 256 rows x 4 chunks = 1024
#pragma unroll
    for (int i = 0; i < 4; i++) {
        int ch = tid + i * 256;
        int r = ch >> 2, c = ch & 3;
        cp_async16(sb + r * FC_ROWB + c * 16, bg + (size_t)r * 512 + c * 8);
    }
}

__global__ __launch_bounds__(256, 1)
void fc_gemm_mma(const float* __restrict__ bias, float* __restrict__ C) {
    extern __shared__ char smem[];
    uint32_t sbase = smem_u32(smem);
    int tid = threadIdx.x, wid = tid >> 5, lane = tid & 31;
    int m0 = blockIdx.x * 128;                       // 16 tiles (fastest -> W L2 reuse)
    int n0 = blockIdx.y * 256;                       // 125 tiles
    int wm = (wid >> 2) * 64;                        // warp m base (0/64)
    int wn = (wid & 3) * 64;                         // warp n base (0..192)

    float acc[4][8][4];
#pragma unroll
    for (int a = 0; a < 4; a++)
#pragma unroll
        for (int b = 0; b < 8; b++)
#pragma unroll
            for (int r = 0; r < 4; r++) acc[a][b][r] = 0.0f;

    // per-lane ldmatrix base offsets within a stage
    uint32_t aOff = (uint32_t)(wm + (lane & 15)) * FC_ROWB + (uint32_t)(lane >> 4) * 16;
    int bn = (lane & 7) + ((lane >> 4) & 1) * 8;
    uint32_t bOff = (uint32_t)(wn + bn) * FC_ROWB + (uint32_t)((lane >> 3) & 1) * 16;

    // prologue: stages 0..2
    fc_load_stage(sbase, tid, m0, n0, 0); CP_COMMIT();
    fc_load_stage(sbase, tid, m0, n0, 1); CP_COMMIT();
    fc_load_stage(sbase, tid, m0, n0, 2); CP_COMMIT();

#pragma unroll 1
    for (int kt = 0; kt < FC_KTILES; kt++) {
        CP_WAIT(2);
        __syncthreads();          // orders slot reuse for the load below too
        if (kt + 3 < FC_KTILES) fc_load_stage(sbase, tid, m0, n0, kt + 3);
        CP_COMMIT();              // empty-commit keeps group count in step

        int slot = kt & 3;
        uint32_t aS = sbase + slot * FC_STAGE_BYTES;
        uint32_t bS = aS + FC_A_STAGE;
#pragma unroll
        for (int ks = 0; ks < 2; ks++) {
            uint32_t k2 = (uint32_t)(ks * 32);       // 16 f16 = 32 bytes
            uint32_t af[4][4];
#pragma unroll
            for (int mb = 0; mb < 4; mb++)
                ldsm_x4(af[mb], aS + aOff + (uint32_t)mb * 16 * FC_ROWB + k2);
            uint32_t bfr[4][4];
#pragma unroll
            for (int nq = 0; nq < 4; nq++)
                ldsm_x4(bfr[nq], bS + bOff + (uint32_t)nq * 16 * FC_ROWB + k2);
#pragma unroll
            for (int mb = 0; mb < 4; mb++)
#pragma unroll
                for (int nb = 0; nb < 8; nb++)
                    mma16816(acc[mb][nb], af[mb],
                             bfr[nb >> 1][(nb & 1) * 2], bfr[nb >> 1][(nb & 1) * 2 + 1]);
        }
    }

    // epilogue: two 128-col passes staged through smem (aliases pipeline bufs)
    float* epi = (float*)smem;                        // [128][132]
    int er = lane >> 2, ec = (lane & 3) * 2;
#pragma unroll 1
    for (int h = 0; h < 2; h++) {
        __syncthreads();
        if (((wid & 3) >> 1) == h) {
            int nbase = wn - h * 128;                 // 0 or 64 within this pass
#pragma unroll
            for (int mb = 0; mb < 4; mb++) {
#pragma unroll
                for (int nb = 0; nb < 8; nb++) {
                    int m = wm + mb * 16 + er;
                    int n = nbase + nb * 8 + ec;
                    *(float2*)&epi[m * 132 + n]       = make_float2(acc[mb][nb][0], acc[mb][nb][1]);
                    *(float2*)&epi[(m + 8) * 132 + n] = make_float2(acc[mb][nb][2], acc[mb][nb][3]);
                }
            }
        }
        __syncthreads();
        float4 bv = *(const float4*)(bias + n0 + h * 128 + lane * 4);
#pragma unroll 1
        for (int r = 0; r < 16; r++) {
            int m = wid * 16 + r;
            float4 v = *(float4*)&epi[m * 132 + lane * 4];
            v.x += bv.x; v.y += bv.y; v.z += bv.z; v.w += bv.w;
            *(float4*)&C[(size_t)(m0 + m) * V_ + n0 + h * 128 + lane * 4] = v;
        }
    }
}

// ---------------- launch ----------------------------------------------------
extern "C" void kernel_launch(void* const* d_in, const int* in_sizes, int n_in,
                              void* d_out, int out_size) {
    const int*   x      = (const int*)d_in[0];
    const float* embed  = (const float*)d_in[1];
    const float* w_ih_f = (const float*)d_in[2];
    const float* w_hh_f = (const float*)d_in[3];
    const float* b_ih_f = (const float*)d_in[4];
    const float* b_hh_f = (const float*)d_in[5];
    const float* w_ih_b = (const float*)d_in[6];
    // d_in[7] = w_hh_b : multiplied by the zero initial state -> unused
    const float* b_ih_b = (const float*)d_in[8];
    const float* b_hh_b = (const float*)d_in[9];
    const float* fc_w   = (const float*)d_in[10];
    const float* fc_b   = (const float*)d_in[11];
    float* out = (float*)d_out;

    cudaFuncSetAttribute(fc_gemm_mma, cudaFuncAttributeMaxDynamicSharedMemorySize, FC_SMEM);

    detect_kernel<<<1, 256>>>(x);
    zero_state<<<16, 256>>>();
    gather_kernel<<<512, 256>>>(x, (const float4*)embed);
    convW<<<V_, 256>>>(fc_w);
    proj_gemm<<<dim3(16, 16), 256>>>(w_ih_f, w_ih_b, b_ih_f, b_hh_f, b_ih_b, b_hh_b);
    hb_kernel<<<2048, 256>>>();
    lstm_persist<<<NCTA_LSTM, 256>>>(w_hh_f);
    convA<<<2048, 256>>>();   // FIXED: full 2048-row coverage (was 512 -> 3/4 of A stale)
    fc_gemm_mma<<<dim3(16, 125), 256, FC_SMEM>>>(fc_b, out);
    (void)in_sizes; (void)n_in; (void)out_size;
}

// round 16
// speedup vs baseline: 2.3652x; 1.1190x over previous
#include <cuda_runtime.h>
#include <cuda_fp16.h>
#include <cstdint>
#include <math.h>

// Problem dims
#define B_  16
#define S_  128
#define BS  2048      // B*S
#define D_  256
#define H_  256
#define V_  32000
#define K2H 512       // 2*H

// FC GEMM (mma.sync fp16, single-term): C[2048,32000] = f16(A)[2048,512] x f16(W)[32000,512]^T
// CTA tile 128(M) x 256(N), 8 warps (2m x 4n), warp tile 64x64.
#define FC_KTILES 16            // 16 x 32 = 512
#define FC_KC 32
#define FC_STAGES 4
#define FC_ROWB 80              // padded smem row bytes (32 f16 = 64B + 16B pad)
#define FC_A_STAGE (128 * FC_ROWB)
#define FC_B_STAGE (256 * FC_ROWB)
#define FC_STAGE_BYTES (FC_A_STAGE + FC_B_STAGE)
#define FC_SMEM (FC_STAGES * FC_STAGE_BYTES)    // 122880

// ---------------- scratch (device globals; no allocation allowed) -----------
__device__ float g_emb[BS * D_];
__device__ float g_pre[BS * 2048];
__device__ float g_h[2][B_ * H_];
__device__ __half g_a2[BS * 512];                // [2048,512] = f16(concat(hf,hb))
__device__ __half g_w2[(size_t)V_ * 512];        // [32000,512] = f16(W)
__device__ int   g_is64;
__device__ int          g_cnt2[64];              // two barrier groups, 128B apart
__device__ volatile int g_flag2[64];

// ---------------- helpers ---------------------------------------------------
__device__ __forceinline__ float sigf(float x) { return 1.0f / (1.0f + expf(-x)); }

__device__ __forceinline__ uint32_t smem_u32(const void* p) {
    uint32_t a;
    asm("{ .reg .u64 t; cvta.to.shared.u64 t, %1; cvt.u32.u64 %0, t; }" : "=r"(a) : "l"(p));
    return a;
}
__device__ __forceinline__ void cp_async16(uint32_t s, const void* g) {
    asm volatile("cp.async.cg.shared.global [%0], [%1], 16;" :: "r"(s), "l"(g));
}
#define CP_COMMIT() asm volatile("cp.async.commit_group;" ::: "memory")
#define CP_WAIT(n)  asm volatile("cp.async.wait_group %0;" :: "n"(n) : "memory")

__device__ __forceinline__ void ldsm_x4(uint32_t* r, uint32_t addr) {
    asm volatile("ldmatrix.sync.aligned.m8n8.x4.shared.b16 {%0,%1,%2,%3}, [%4];"
                 : "=r"(r[0]), "=r"(r[1]), "=r"(r[2]), "=r"(r[3]) : "r"(addr));
}
__device__ __forceinline__ void mma16816(float* c, const uint32_t* a,
                                         uint32_t b0, uint32_t b1) {
    asm volatile(
        "mma.sync.aligned.m16n8k16.row.col.f32.f16.f16.f32 "
        "{%0,%1,%2,%3}, {%4,%5,%6,%7}, {%8,%9}, {%0,%1,%2,%3};"
        : "+f"(c[0]), "+f"(c[1]), "+f"(c[2]), "+f"(c[3])
        : "r"(a[0]), "r"(a[1]), "r"(a[2]), "r"(a[3]), "r"(b0), "r"(b1));
}

// ---------------- dtype detect: int64 tokens have zero high words -----------
__global__ void detect_kernel(const int* __restrict__ xi) {
    __shared__ int red[256];
    int acc = 0;
    for (int i = threadIdx.x; i < 1024; i += 256) acc |= xi[2 * i + 1];
    red[threadIdx.x] = acc;
    __syncthreads();
    for (int s = 128; s > 0; s >>= 1) {
        if (threadIdx.x < s) red[threadIdx.x] |= red[threadIdx.x + s];
        __syncthreads();
    }
    if (threadIdx.x == 0) g_is64 = (red[0] == 0) ? 1 : 0;
}

// ---------------- per-launch state init (replay-deterministic) --------------
__global__ void zero_state() {
    int i = blockIdx.x * 256 + threadIdx.x;
    if (i < B_ * H_) g_h[0][i] = 0.0f;
    if (i < 64) { g_cnt2[i] = 0; g_flag2[i] = 0; }
}

// ---------------- embedding gather ------------------------------------------
__global__ void gather_kernel(const int* __restrict__ xi,
                              const float4* __restrict__ emb4) {
    int idx = blockIdx.x * 256 + threadIdx.x;
    int r = idx >> 6, c = idx & 63;
    long long tok;
    if (g_is64) tok = ((const long long*)xi)[r];
    else        tok = (long long)xi[r];
    ((float4*)g_emb)[r * 64 + c] = emb4[(size_t)tok * 64 + c];
}

// ---------------- input projection GEMM: [2048,256] x [2048,256]^T ----------
__global__ __launch_bounds__(256, 2)
void proj_gemm(const float* __restrict__ wf, const float* __restrict__ wb,
               const float* __restrict__ bif, const float* __restrict__ bhf,
               const float* __restrict__ bib, const float* __restrict__ bhb) {
    __shared__ float As[16][132];
    __shared__ float Bs[16][132];
    int m0 = blockIdx.y * 128, n0 = blockIdx.x * 128;
    const float *Bw, *bb1, *bb2;
    if (n0 < 1024) { Bw = wf + (size_t)n0 * 256;          bb1 = bif + n0;          bb2 = bhf + n0; }
    else           { Bw = wb + (size_t)(n0 - 1024) * 256; bb1 = bib + (n0 - 1024); bb2 = bhb + (n0 - 1024); }

    int tid = threadIdx.x;
    int tm = (tid >> 4) << 3, tn = (tid & 15) << 3;
    float acc[8][8] = {};

    for (int k0 = 0; k0 < 256; k0 += 16) {
#pragma unroll
        for (int i = 0; i < 2; i++) {
            int q = tid + i * 256;
            int row = q >> 2, qc = q & 3;
            float4 va = *(const float4*)(g_emb + (size_t)(m0 + row) * 256 + k0 + qc * 4);
            float4 vb = *(const float4*)(Bw + (size_t)row * 256 + k0 + qc * 4);
            As[qc * 4 + 0][row] = va.x; As[qc * 4 + 1][row] = va.y;
            As[qc * 4 + 2][row] = va.z; As[qc * 4 + 3][row] = va.w;
            Bs[qc * 4 + 0][row] = vb.x; Bs[qc * 4 + 1][row] = vb.y;
            Bs[qc * 4 + 2][row] = vb.z; Bs[qc * 4 + 3][row] = vb.w;
        }
        __syncthreads();
#pragma unroll
        for (int k = 0; k < 16; k++) {
            float a[8], b[8];
            *(float4*)(a)     = *(const float4*)&As[k][tm];
            *(float4*)(a + 4) = *(const float4*)&As[k][tm + 4];
            *(float4*)(b)     = *(const float4*)&Bs[k][tn];
            *(float4*)(b + 4) = *(const float4*)&Bs[k][tn + 4];
#pragma unroll
            for (int ii = 0; ii < 8; ii++)
#pragma unroll
                for (int jj = 0; jj < 8; jj++) acc[ii][jj] += a[ii] * b[jj];
        }
        __syncthreads();
    }
#pragma unroll
    for (int ii = 0; ii < 8; ii++) {
        int r = m0 + tm + ii;
#pragma unroll
        for (int jj = 0; jj < 8; jj += 4) {
            float4 o;
            o.x = acc[ii][jj + 0] + bb1[tn + jj + 0] + bb2[tn + jj + 0];
            o.y = acc[ii][jj + 1] + bb1[tn + jj + 1] + bb2[tn + jj + 1];
            o.z = acc[ii][jj + 2] + bb1[tn + jj + 2] + bb2[tn + jj + 2];
            o.w = acc[ii][jj + 3] + bb1[tn + jj + 3] + bb2[tn + jj + 3];
            *(float4*)(g_pre + (size_t)r * 2048 + n0 + tn + jj) = o;
        }
    }
}

// ---------------- backward direction: single cell step (writes fp16 A) ------
__global__ void hb_kernel() {
    int idx = blockIdx.x * 256 + threadIdx.x;
    int r = idx >> 8, j = idx & 255;
    const float* p = g_pre + (size_t)r * 2048 + 1024;
    float ig = sigf(p[j]);
    float gg = tanhf(p[512 + j]);
    float og = sigf(p[768 + j]);
    g_a2[(size_t)r * 512 + 256 + j] = __float2half_rn(og * tanhf(ig * gg));
}

// ---------------- forward LSTM: persistent, batch-split into 2 groups -------
// 128 CTAs: group g = blockIdx.x>>6 owns batches g*8..g*8+7 (independent
// recurrences -> independent 64-CTA barriers). CTA owns 4 hidden units
// (16 gate rows, smem). Dots are 2-thread (k-halved) + shfl reduce.
__global__ __launch_bounds__(256, 1)
void lstm_persist(const float* __restrict__ w_hh) {
    __shared__ float sw[16][264];
    __shared__ float sh[8][264];
    __shared__ float spre[4][8][4];
    __shared__ int sense;
    int tid = threadIdx.x;
    int g  = blockIdx.x >> 6;            // batch group 0/1
    int b0 = g * 8;
    int j0 = (blockIdx.x & 63) * 4;      // 4 hidden units
    if (tid == 0) sense = 0;

    // weights: 16 gate rows x 256 (1024 float4, 4 per thread)
#pragma unroll
    for (int i = 0; i < 4; i++) {
        int q = tid + i * 256;
        int rr = q >> 6, kc = q & 63;
        int gi = rr >> 2, jj = rr & 3;
        int grow = gi * 256 + j0 + jj;
        float4 wv = ((const float4*)w_hh)[grow * 64 + kc];
        *(float4*)&sw[rr][kc * 4] = wv;
    }

    float creg = 0.0f;                   // cell state for tid<32: (b=tid>>2, jj=tid&3)

    int d  = tid >> 1;                   // dot id 0..127
    int kh = tid & 1;                    // k half
    int rr = d & 15, bb = d >> 4;        // gate row, batch (0..7)
    int gi = rr >> 2, jj = rr & 3;

    for (int t = 0; t < S_; t++) {
        const float4* __restrict__ h_in = (const float4*)g_h[t & 1];
        float* h_out = g_h[(t + 1) & 1];

        // load this group's 8 batches of h (512 float4, 2 per thread), via L2
#pragma unroll
        for (int i = 0; i < 2; i++) {
            int q = tid + i * 256;
            int r8 = q >> 6, kc = q & 63;
            float4 hv = __ldcg(h_in + (b0 + r8) * 64 + kc);
            *(float4*)&sh[r8][kc * 4] = hv;
        }
        __syncthreads();

        {   // 2-thread dot: interleaved k (thread kh takes float4s 2*kc+kh)
            const float4* wr = (const float4*)&sw[rr][0];
            const float4* hr = (const float4*)&sh[bb][0];
            float acc = 0.0f;
#pragma unroll 8
            for (int kc = 0; kc < 32; kc++) {
                float4 w = wr[2 * kc + kh], h = hr[2 * kc + kh];
                acc += w.x * h.x + w.y * h.y + w.z * h.z + w.w * h.w;
            }
            acc += __shfl_xor_sync(0xFFFFFFFFu, acc, 1);
            if (kh == 0) {
                int r = (b0 + bb) * S_ + t;
                acc += g_pre[(size_t)r * 2048 + gi * 256 + j0 + jj];
                spre[gi][bb][jj] = acc;
            }
        }
        __syncthreads();

        if (tid < 32) {
            int b = tid >> 2, j2 = tid & 3;
            int j = j0 + j2;
            float ig = sigf(spre[0][b][j2]);
            float fg = sigf(spre[1][b][j2]);
            float gg = tanhf(spre[2][b][j2]);
            float og = sigf(spre[3][b][j2]);
            creg = fg * creg + ig * gg;
            float h = og * tanhf(creg);
            h_out[(b0 + b) * 256 + j] = h;
            g_a2[(size_t)((b0 + b) * S_ + t) * 512 + j] = __float2half_rn(h);
            __threadfence();             // release h_out before barrier arrival
        }

        // -------- per-group global barrier (sense-reversing) --------
        __syncthreads();
        if (tid == 0) {
            int s = sense ^ 1;
            sense = s;
            int slot = g * 32;           // 128B-separated counters
            int v = atomicAdd(&g_cnt2[slot], 1);
            if (v == 63) {
                g_cnt2[slot] = 0;
                __threadfence();
                g_flag2[slot] = s;
            } else {
                while (g_flag2[slot] != s) __nanosleep(32);
            }
            __threadfence();             // acquire before next step's h reads
        }
        __syncthreads();
    }
}

// ---------------- fp32 -> fp16 W conversion ----------------------------------
__global__ void convW(const float* __restrict__ W) {
    size_t idx = (size_t)blockIdx.x * 256 + threadIdx.x;   // 32000 x 256 float2
    size_t r = idx >> 8; int kp = (int)(idx & 255);
    float2 v = *(const float2*)(W + r * 512 + kp * 2);
    __half2* o = (__half2*)(g_w2 + r * 512);
    o[kp] = __halves2half2(__float2half_rn(v.x), __float2half_rn(v.y));
}

// ---------------- FC GEMM via mma.sync (fp16, single-term) -------------------
// CTA 128x256, 8 warps (2m x 4n), warp tile 64x64, 4-stage cp.async, KC=32.
static __device__ __forceinline__
void fc_load_stage(uint32_t sbase, int tid, int m0, int n0, int kt) {
    int slot = kt & 3;
    uint32_t sa = sbase + slot * FC_STAGE_BYTES;
    uint32_t sb = sa + FC_A_STAGE;
    int ke = kt * FC_KC;
    const __half* ag = g_a2 + (size_t)m0 * 512 + ke;
    const __half* bg = g_w2 + (size_t)n0 * 512 + ke;
#pragma unroll
    for (int i = 0; i < 2; i++) {
        int ch = tid + i * 256;
        int r = ch >> 2, c = ch & 3;
        cp_async16(sa + r * FC_ROWB + c * 16, ag + (size_t)r * 512 + c * 8);
    }
#pragma unroll
    for (int i = 0; i < 4; i++) {
        int ch = tid + i * 256;
        int r = ch >> 2, c = ch & 3;
        cp_async16(sb + r * FC_ROWB + c * 16, bg + (size_t)r * 512 + c * 8);
    }
}

__global__ __launch_bounds__(256, 1)
void fc_gemm_mma(const float* __restrict__ bias, float* __restrict__ C) {
    extern __shared__ char smem[];
    uint32_t sbase = smem_u32(smem);
    int tid = threadIdx.x, wid = tid >> 5, lane = tid & 31;
    int m0 = blockIdx.x * 128;                       // 16 tiles (fastest -> W L2 reuse)
    int n0 = blockIdx.y * 256;                       // 125 tiles
    int wm = (wid >> 2) * 64;
    int wn = (wid & 3) * 64;

    float acc[4][8][4];
#pragma unroll
    for (int a = 0; a < 4; a++)
#pragma unroll
        for (int b = 0; b < 8; b++)
#pragma unroll
            for (int r = 0; r < 4; r++) acc[a][b][r] = 0.0f;

    uint32_t aOff = (uint32_t)(wm + (lane & 15)) * FC_ROWB + (uint32_t)(lane >> 4) * 16;
    int bn = (lane & 7) + ((lane >> 4) & 1) * 8;
    uint32_t bOff = (uint32_t)(wn + bn) * FC_ROWB + (uint32_t)((lane >> 3) & 1) * 16;

    fc_load_stage(sbase, tid, m0, n0, 0); CP_COMMIT();
    fc_load_stage(sbase, tid, m0, n0, 1); CP_COMMIT();
    fc_load_stage(sbase, tid, m0, n0, 2); CP_COMMIT();

#pragma unroll 1
    for (int kt = 0; kt < FC_KTILES; kt++) {
        CP_WAIT(2);
        __syncthreads();
        if (kt + 3 < FC_KTILES) fc_load_stage(sbase, tid, m0, n0, kt + 3);
        CP_COMMIT();

        int slot = kt & 3;
        uint32_t aS = sbase + slot * FC_STAGE_BYTES;
        uint32_t bS = aS + FC_A_STAGE;
#pragma unroll
        for (int ks = 0; ks < 2; ks++) {
            uint32_t k2 = (uint32_t)(ks * 32);
            uint32_t af[4][4];
#pragma unroll
            for (int mb = 0; mb < 4; mb++)
                ldsm_x4(af[mb], aS + aOff + (uint32_t)mb * 16 * FC_ROWB + k2);
            uint32_t bfr[4][4];
#pragma unroll
            for (int nq = 0; nq < 4; nq++)
                ldsm_x4(bfr[nq], bS + bOff + (uint32_t)nq * 16 * FC_ROWB + k2);
#pragma unroll
            for (int mb = 0; mb < 4; mb++)
#pragma unroll
                for (int nb = 0; nb < 8; nb++)
                    mma16816(acc[mb][nb], af[mb],
                             bfr[nb >> 1][(nb & 1) * 2], bfr[nb >> 1][(nb & 1) * 2 + 1]);
        }
    }

    // epilogue: direct register->global stores (32B-sector aligned float2;
    // L2 write-combines to full lines). No smem staging, no syncs.
    int er = lane >> 2, ec = (lane & 3) * 2;
    float2 bv[8];
#pragma unroll
    for (int nb = 0; nb < 8; nb++)
        bv[nb] = *(const float2*)(bias + n0 + wn + nb * 8 + ec);
#pragma unroll
    for (int mb = 0; mb < 4; mb++) {
        size_t m = (size_t)(m0 + wm + mb * 16 + er);
#pragma unroll
        for (int nb = 0; nb < 8; nb++) {
            int n = n0 + wn + nb * 8 + ec;
            float2 v0 = make_float2(acc[mb][nb][0] + bv[nb].x, acc[mb][nb][1] + bv[nb].y);
            float2 v1 = make_float2(acc[mb][nb][2] + bv[nb].x, acc[mb][nb][3] + bv[nb].y);
            *(float2*)&C[m * V_ + n]       = v0;
            *(float2*)&C[(m + 8) * V_ + n] = v1;
        }
    }
}

// ---------------- launch ----------------------------------------------------
extern "C" void kernel_launch(void* const* d_in, const int* in_sizes, int n_in,
                              void* d_out, int out_size) {
    const int*   x      = (const int*)d_in[0];
    const float* embed  = (const float*)d_in[1];
    const float* w_ih_f = (const float*)d_in[2];
    const float* w_hh_f = (const float*)d_in[3];
    const float* b_ih_f = (const float*)d_in[4];
    const float* b_hh_f = (const float*)d_in[5];
    const float* w_ih_b = (const float*)d_in[6];
    // d_in[7] = w_hh_b : multiplied by the zero initial state -> unused
    const float* b_ih_b = (const float*)d_in[8];
    const float* b_hh_b = (const float*)d_in[9];
    const float* fc_w   = (const float*)d_in[10];
    const float* fc_b   = (const float*)d_in[11];
    float* out = (float*)d_out;

    cudaFuncSetAttribute(fc_gemm_mma, cudaFuncAttributeMaxDynamicSharedMemorySize, FC_SMEM);

    detect_kernel<<<1, 256>>>(x);
    zero_state<<<16, 256>>>();
    gather_kernel<<<512, 256>>>(x, (const float4*)embed);
    convW<<<V_, 256>>>(fc_w);
    proj_gemm<<<dim3(16, 16), 256>>>(w_ih_f, w_ih_b, b_ih_f, b_hh_f, b_ih_b, b_hh_b);
    hb_kernel<<<2048, 256>>>();
    lstm_persist<<<128, 256>>>(w_hh_f);
    fc_gemm_mma<<<dim3(16, 125), 256, FC_SMEM>>>(fc_b, out);
    (void)in_sizes; (void)n_in; (void)out_size;
}

// round 17
// speedup vs baseline: 2.3940x; 1.0122x over previous
#include <cuda_runtime.h>
#include <cuda_fp16.h>
#include <cstdint>
#include <math.h>

// Problem dims
#define B_  16
#define S_  128
#define BS  2048      // B*S
#define D_  256
#define H_  256
#define V_  32000
#define K2H 512       // 2*H

// FC GEMM (mma.sync fp16, single-term): C[2048,32000] = f16(A)[2048,512] x f16(W)[32000,512]^T
// PERSISTENT: 148 CTAs, each walks tiles g = bid + 148*i (m fastest -> W L2 share).
// 16 k-iters/tile % 4 stages == 0 -> cp.async ring is continuous across tiles.
#define FC_KTILES 16            // 16 x 32 = 512
#define FC_KC 32
#define FC_STAGES 4
#define FC_ROWB 80              // padded smem row bytes (32 f16 = 64B + 16B pad)
#define FC_A_STAGE (128 * FC_ROWB)
#define FC_B_STAGE (256 * FC_ROWB)
#define FC_STAGE_BYTES (FC_A_STAGE + FC_B_STAGE)
#define FC_SMEM (FC_STAGES * FC_STAGE_BYTES)    // 122880
#define FC_NCTA 148
#define FC_NTILES 2000          // 16 m-tiles x 125 n-tiles

// ---------------- scratch (device globals; no allocation allowed) -----------
__device__ float g_emb[BS * D_];
__device__ float g_pre[BS * 2048];
__device__ float g_h[2][B_ * H_];
__device__ __half g_a2[BS * 512];                // [2048,512] = f16(concat(hf,hb))
__device__ __half g_w2[(size_t)V_ * 512];        // [32000,512] = f16(W)
__device__ int   g_is64;
__device__ int          g_cnt2[64];              // two barrier groups, 128B apart
__device__ volatile int g_flag2[64];

// ---------------- helpers ---------------------------------------------------
__device__ __forceinline__ float sigf(float x) { return 1.0f / (1.0f + expf(-x)); }

__device__ __forceinline__ uint32_t smem_u32(const void* p) {
    uint32_t a;
    asm("{ .reg .u64 t; cvta.to.shared.u64 t, %1; cvt.u32.u64 %0, t; }" : "=r"(a) : "l"(p));
    return a;
}
__device__ __forceinline__ void cp_async16(uint32_t s, const void* g) {
    asm volatile("cp.async.cg.shared.global [%0], [%1], 16;" :: "r"(s), "l"(g));
}
#define CP_COMMIT() asm volatile("cp.async.commit_group;" ::: "memory")
#define CP_WAIT(n)  asm volatile("cp.async.wait_group %0;" :: "n"(n) : "memory")

__device__ __forceinline__ void ldsm_x4(uint32_t* r, uint32_t addr) {
    asm volatile("ldmatrix.sync.aligned.m8n8.x4.shared.b16 {%0,%1,%2,%3}, [%4];"
                 : "=r"(r[0]), "=r"(r[1]), "=r"(r[2]), "=r"(r[3]) : "r"(addr));
}
__device__ __forceinline__ void mma16816(float* c, const uint32_t* a,
                                         uint32_t b0, uint32_t b1) {
    asm volatile(
        "mma.sync.aligned.m16n8k16.row.col.f32.f16.f16.f32 "
        "{%0,%1,%2,%3}, {%4,%5,%6,%7}, {%8,%9}, {%0,%1,%2,%3};"
        : "+f"(c[0]), "+f"(c[1]), "+f"(c[2]), "+f"(c[3])
        : "r"(a[0]), "r"(a[1]), "r"(a[2]), "r"(a[3]), "r"(b0), "r"(b1));
}

// ---------------- dtype detect: int64 tokens have zero high words -----------
__global__ void detect_kernel(const int* __restrict__ xi) {
    __shared__ int red[256];
    int acc = 0;
    for (int i = threadIdx.x; i < 1024; i += 256) acc |= xi[2 * i + 1];
    red[threadIdx.x] = acc;
    __syncthreads();
    for (int s = 128; s > 0; s >>= 1) {
        if (threadIdx.x < s) red[threadIdx.x] |= red[threadIdx.x + s];
        __syncthreads();
    }
    if (threadIdx.x == 0) g_is64 = (red[0] == 0) ? 1 : 0;
}

// ---------------- per-launch state init (replay-deterministic) --------------
__global__ void zero_state() {
    int i = blockIdx.x * 256 + threadIdx.x;
    if (i < B_ * H_) g_h[0][i] = 0.0f;
    if (i < 64) { g_cnt2[i] = 0; g_flag2[i] = 0; }
}

// ---------------- embedding gather ------------------------------------------
__global__ void gather_kernel(const int* __restrict__ xi,
                              const float4* __restrict__ emb4) {
    int idx = blockIdx.x * 256 + threadIdx.x;
    int r = idx >> 6, c = idx & 63;
    long long tok;
    if (g_is64) tok = ((const long long*)xi)[r];
    else        tok = (long long)xi[r];
    ((float4*)g_emb)[r * 64 + c] = emb4[(size_t)tok * 64 + c];
}

// ---------------- input projection GEMM: [2048,256] x [2048,256]^T ----------
__global__ __launch_bounds__(256, 2)
void proj_gemm(const float* __restrict__ wf, const float* __restrict__ wb,
               const float* __restrict__ bif, const float* __restrict__ bhf,
               const float* __restrict__ bib, const float* __restrict__ bhb) {
    __shared__ float As[16][132];
    __shared__ float Bs[16][132];
    int m0 = blockIdx.y * 128, n0 = blockIdx.x * 128;
    const float *Bw, *bb1, *bb2;
    if (n0 < 1024) { Bw = wf + (size_t)n0 * 256;          bb1 = bif + n0;          bb2 = bhf + n0; }
    else           { Bw = wb + (size_t)(n0 - 1024) * 256; bb1 = bib + (n0 - 1024); bb2 = bhb + (n0 - 1024); }

    int tid = threadIdx.x;
    int tm = (tid >> 4) << 3, tn = (tid & 15) << 3;
    float acc[8][8] = {};

    for (int k0 = 0; k0 < 256; k0 += 16) {
#pragma unroll
        for (int i = 0; i < 2; i++) {
            int q = tid + i * 256;
            int row = q >> 2, qc = q & 3;
            float4 va = *(const float4*)(g_emb + (size_t)(m0 + row) * 256 + k0 + qc * 4);
            float4 vb = *(const float4*)(Bw + (size_t)row * 256 + k0 + qc * 4);
            As[qc * 4 + 0][row] = va.x; As[qc * 4 + 1][row] = va.y;
            As[qc * 4 + 2][row] = va.z; As[qc * 4 + 3][row] = va.w;
            Bs[qc * 4 + 0][row] = vb.x; Bs[qc * 4 + 1][row] = vb.y;
            Bs[qc * 4 + 2][row] = vb.z; Bs[qc * 4 + 3][row] = vb.w;
        }
        __syncthreads();
#pragma unroll
        for (int k = 0; k < 16; k++) {
            float a[8], b[8];
            *(float4*)(a)     = *(const float4*)&As[k][tm];
            *(float4*)(a + 4) = *(const float4*)&As[k][tm + 4];
            *(float4*)(b)     = *(const float4*)&Bs[k][tn];
            *(float4*)(b + 4) = *(const float4*)&Bs[k][tn + 4];
#pragma unroll
            for (int ii = 0; ii < 8; ii++)
#pragma unroll
                for (int jj = 0; jj < 8; jj++) acc[ii][jj] += a[ii] * b[jj];
        }
        __syncthreads();
    }
#pragma unroll
    for (int ii = 0; ii < 8; ii++) {
        int r = m0 + tm + ii;
#pragma unroll
        for (int jj = 0; jj < 8; jj += 4) {
            float4 o;
            o.x = acc[ii][jj + 0] + bb1[tn + jj + 0] + bb2[tn + jj + 0];
            o.y = acc[ii][jj + 1] + bb1[tn + jj + 1] + bb2[tn + jj + 1];
            o.z = acc[ii][jj + 2] + bb1[tn + jj + 2] + bb2[tn + jj + 2];
            o.w = acc[ii][jj + 3] + bb1[tn + jj + 3] + bb2[tn + jj + 3];
            *(float4*)(g_pre + (size_t)r * 2048 + n0 + tn + jj) = o;
        }
    }
}

// ---------------- backward direction: single cell step (writes fp16 A) ------
__global__ void hb_kernel() {
    int idx = blockIdx.x * 256 + threadIdx.x;
    int r = idx >> 8, j = idx & 255;
    const float* p = g_pre + (size_t)r * 2048 + 1024;
    float ig = sigf(p[j]);
    float gg = tanhf(p[512 + j]);
    float og = sigf(p[768 + j]);
    g_a2[(size_t)r * 512 + 256 + j] = __float2half_rn(og * tanhf(ig * gg));
}

// ---------------- forward LSTM: persistent, batch-split into 2 groups -------
__global__ __launch_bounds__(256, 1)
void lstm_persist(const float* __restrict__ w_hh) {
    __shared__ float sw[16][264];
    __shared__ float sh[8][264];
    __shared__ float spre[4][8][4];
    __shared__ int sense;
    int tid = threadIdx.x;
    int g  = blockIdx.x >> 6;            // batch group 0/1
    int b0 = g * 8;
    int j0 = (blockIdx.x & 63) * 4;      // 4 hidden units
    if (tid == 0) sense = 0;

#pragma unroll
    for (int i = 0; i < 4; i++) {
        int q = tid + i * 256;
        int rr = q >> 6, kc = q & 63;
        int gi = rr >> 2, jj = rr & 3;
        int grow = gi * 256 + j0 + jj;
        float4 wv = ((const float4*)w_hh)[grow * 64 + kc];
        *(float4*)&sw[rr][kc * 4] = wv;
    }

    float creg = 0.0f;

    int d  = tid >> 1;
    int kh = tid & 1;
    int rr = d & 15, bb = d >> 4;
    int gi = rr >> 2, jj = rr & 3;

    for (int t = 0; t < S_; t++) {
        const float4* __restrict__ h_in = (const float4*)g_h[t & 1];
        float* h_out = g_h[(t + 1) & 1];

#pragma unroll
        for (int i = 0; i < 2; i++) {
            int q = tid + i * 256;
            int r8 = q >> 6, kc = q & 63;
            float4 hv = __ldcg(h_in + (b0 + r8) * 64 + kc);
            *(float4*)&sh[r8][kc * 4] = hv;
        }
        __syncthreads();

        {
            const float4* wr = (const float4*)&sw[rr][0];
            const float4* hr = (const float4*)&sh[bb][0];
            float acc = 0.0f;
#pragma unroll 8
            for (int kc = 0; kc < 32; kc++) {
                float4 w = wr[2 * kc + kh], h = hr[2 * kc + kh];
                acc += w.x * h.x + w.y * h.y + w.z * h.z + w.w * h.w;
            }
            acc += __shfl_xor_sync(0xFFFFFFFFu, acc, 1);
            if (kh == 0) {
                int r = (b0 + bb) * S_ + t;
                acc += g_pre[(size_t)r * 2048 + gi * 256 + j0 + jj];
                spre[gi][bb][jj] = acc;
            }
        }
        __syncthreads();

        if (tid < 32) {
            int b = tid >> 2, j2 = tid & 3;
            int j = j0 + j2;
            float ig = sigf(spre[0][b][j2]);
            float fg = sigf(spre[1][b][j2]);
            float gg = tanhf(spre[2][b][j2]);
            float og = sigf(spre[3][b][j2]);
            creg = fg * creg + ig * gg;
            float h = og * tanhf(creg);
            h_out[(b0 + b) * 256 + j] = h;
            g_a2[(size_t)((b0 + b) * S_ + t) * 512 + j] = __float2half_rn(h);
            __threadfence();
        }

        __syncthreads();
        if (tid == 0) {
            int s = sense ^ 1;
            sense = s;
            int slot = g * 32;
            int v = atomicAdd(&g_cnt2[slot], 1);
            if (v == 63) {
                g_cnt2[slot] = 0;
                __threadfence();
                g_flag2[slot] = s;
            } else {
                while (g_flag2[slot] != s) __nanosleep(32);
            }
            __threadfence();
        }
        __syncthreads();
    }
}

// ---------------- fp32 -> fp16 W conversion ----------------------------------
__global__ void convW(const float* __restrict__ W) {
    size_t idx = (size_t)blockIdx.x * 256 + threadIdx.x;
    size_t r = idx >> 8; int kp = (int)(idx & 255);
    float2 v = *(const float2*)(W + r * 512 + kp * 2);
    __half2* o = (__half2*)(g_w2 + r * 512);
    o[kp] = __halves2half2(__float2half_rn(v.x), __float2half_rn(v.y));
}

// ---------------- FC GEMM: persistent mma.sync (fp16, single-term) ----------
// Tile g: m0 = (g&15)*128, n0 = (g>>4)*256. Ring slot = kt&3 (16%4==0 so the
// pipeline is continuous across tiles: loads for next tile's kt 0..2 issue
// during current tile's kt 13..15; epilogue stores overlap those loads).
static __device__ __forceinline__
void fc_load_stage(uint32_t sbase, int tid, int m0, int n0, int kt) {
    int slot = kt & 3;
    uint32_t sa = sbase + slot * FC_STAGE_BYTES;
    uint32_t sb = sa + FC_A_STAGE;
    int ke = kt * FC_KC;
    const __half* ag = g_a2 + (size_t)m0 * 512 + ke;
    const __half* bg = g_w2 + (size_t)n0 * 512 + ke;
#pragma unroll
    for (int i = 0; i < 2; i++) {
        int ch = tid + i * 256;
        int r = ch >> 2, c = ch & 3;
        cp_async16(sa + r * FC_ROWB + c * 16, ag + (size_t)r * 512 + c * 8);
    }
#pragma unroll
    for (int i = 0; i < 4; i++) {
        int ch = tid + i * 256;
        int r = ch >> 2, c = ch & 3;
        cp_async16(sb + r * FC_ROWB + c * 16, bg + (size_t)r * 512 + c * 8);
    }
}

__global__ __launch_bounds__(256, 1)
void fc_gemm_mma(const float* __restrict__ bias, float* __restrict__ C) {
    extern __shared__ char smem[];
    uint32_t sbase = smem_u32(smem);
    int tid = threadIdx.x, wid = tid >> 5, lane = tid & 31;
    int bid = blockIdx.x;
    int wm = (wid >> 2) * 64;
    int wn = (wid & 3) * 64;

    int ntiles = (FC_NTILES - bid + FC_NCTA - 1) / FC_NCTA;   // 13 or 14

    float acc[4][8][4];
#pragma unroll
    for (int a = 0; a < 4; a++)
#pragma unroll
        for (int b = 0; b < 8; b++)
#pragma unroll
            for (int r = 0; r < 4; r++) acc[a][b][r] = 0.0f;

    uint32_t aOff = (uint32_t)(wm + (lane & 15)) * FC_ROWB + (uint32_t)(lane >> 4) * 16;
    int bn = (lane & 7) + ((lane >> 4) & 1) * 8;
    uint32_t bOff = (uint32_t)(wn + bn) * FC_ROWB + (uint32_t)((lane >> 3) & 1) * 16;

    int er = lane >> 2, ec = (lane & 3) * 2;

    // prologue: first tile's k-iters 0..2 (every CTA has >= 13 tiles)
    {
        int g0 = bid;
        int m0 = (g0 & 15) << 7, n0 = (g0 >> 4) << 8;
        fc_load_stage(sbase, tid, m0, n0, 0); CP_COMMIT();
        fc_load_stage(sbase, tid, m0, n0, 1); CP_COMMIT();
        fc_load_stage(sbase, tid, m0, n0, 2); CP_COMMIT();
    }

#pragma unroll 1
    for (int it = 0; it < ntiles; it++) {
        int gcur = bid + it * FC_NCTA;
        int m0 = (gcur & 15) << 7, n0 = (gcur >> 4) << 8;
        int gnx = gcur + FC_NCTA;
        bool has_next = (gnx < FC_NTILES);
        int nm0 = (gnx & 15) << 7, nn0 = (gnx >> 4) << 8;

#pragma unroll 1
        for (int kt = 0; kt < FC_KTILES; kt++) {
            CP_WAIT(2);
            __syncthreads();              // orders slot reuse for the load below
            int lkt = kt + 3;
            if (lkt < FC_KTILES)          fc_load_stage(sbase, tid, m0, n0, lkt);
            else if (has_next)            fc_load_stage(sbase, tid, nm0, nn0, lkt - FC_KTILES);
            CP_COMMIT();                  // exactly one commit per iter

            int slot = kt & 3;
            uint32_t aS = sbase + slot * FC_STAGE_BYTES;
            uint32_t bS = aS + FC_A_STAGE;
#pragma unroll
            for (int ks = 0; ks < 2; ks++) {
                uint32_t k2 = (uint32_t)(ks * 32);
                uint32_t af[4][4];
#pragma unroll
                for (int mb = 0; mb < 4; mb++)
                    ldsm_x4(af[mb], aS + aOff + (uint32_t)mb * 16 * FC_ROWB + k2);
                uint32_t bfr[4][4];
#pragma unroll
                for (int nq = 0; nq < 4; nq++)
                    ldsm_x4(bfr[nq], bS + bOff + (uint32_t)nq * 16 * FC_ROWB + k2);
#pragma unroll
                for (int mb = 0; mb < 4; mb++)
#pragma unroll
                    for (int nb = 0; nb < 8; nb++)
                        mma16816(acc[mb][nb], af[mb],
                                 bfr[nb >> 1][(nb & 1) * 2], bfr[nb >> 1][(nb & 1) * 2 + 1]);
            }
        }

        // epilogue: direct register->global stores; no smem, no syncs ->
        // overlaps the already-issued next-tile cp.async loads.
        float2 bv[8];
#pragma unroll
        for (int nb = 0; nb < 8; nb++)
            bv[nb] = *(const float2*)(bias + n0 + wn + nb * 8 + ec);
#pragma unroll
        for (int mb = 0; mb < 4; mb++) {
            size_t m = (size_t)(m0 + wm + mb * 16 + er);
#pragma unroll
            for (int nb = 0; nb < 8; nb++) {
                int n = n0 + wn + nb * 8 + ec;
                float2 v0 = make_float2(acc[mb][nb][0] + bv[nb].x, acc[mb][nb][1] + bv[nb].y);
                float2 v1 = make_float2(acc[mb][nb][2] + bv[nb].x, acc[mb][nb][3] + bv[nb].y);
                *(float2*)&C[m * V_ + n]       = v0;
                *(float2*)&C[(m + 8) * V_ + n] = v1;
                acc[mb][nb][0] = 0.0f; acc[mb][nb][1] = 0.0f;
                acc[mb][nb][2] = 0.0f; acc[mb][nb][3] = 0.0f;
            }
        }
    }
}

// ---------------- launch ----------------------------------------------------
extern "C" void kernel_launch(void* const* d_in, const int* in_sizes, int n_in,
                              void* d_out, int out_size) {
    const int*   x      = (const int*)d_in[0];
    const float* embed  = (const float*)d_in[1];
    const float* w_ih_f = (const float*)d_in[2];
    const float* w_hh_f = (const float*)d_in[3];
    const float* b_ih_f = (const float*)d_in[4];
    const float* b_hh_f = (const float*)d_in[5];
    const float* w_ih_b = (const float*)d_in[6];
    // d_in[7] = w_hh_b : multiplied by the zero initial state -> unused
    const float* b_ih_b = (const float*)d_in[8];
    const float* b_hh_b = (const float*)d_in[9];
    const float* fc_w   = (const float*)d_in[10];
    const float* fc_b   = (const float*)d_in[11];
    float* out = (float*)d_out;

    cudaFuncSetAttribute(fc_gemm_mma, cudaFuncAttributeMaxDynamicSharedMemorySize, FC_SMEM);

    detect_kernel<<<1, 256>>>(x);
    zero_state<<<16, 256>>>();
    gather_kernel<<<512, 256>>>(x, (const float4*)embed);
    convW<<<V_, 256>>>(fc_w);
    proj_gemm<<<dim3(16, 16), 256>>>(w_ih_f, w_ih_b, b_ih_f, b_hh_f, b_ih_b, b_hh_b);
    hb_kernel<<<2048, 256>>>();
    lstm_persist<<<128, 256>>>(w_hh_f);
    fc_gemm_mma<<<FC_NCTA, 256, FC_SMEM>>>(fc_b, out);
    (void)in_sizes; (void)n_in; (void)out_size;
}